// round 1
// baseline (speedup 1.0000x reference)
#include <cuda_runtime.h>
#include <math.h>

#define BATCH   32
#define SEQ     197
#define EMB     768
#define EMB3    2304
#define HEADS   12
#define HD      64
#define KW      197
#define NLAYERS 12
#define HIDDEN  3072
#define TOK     (BATCH*SEQ)       // 6304
#define BH      (BATCH*HEADS)     // 384
#define ROWSA   (BH*SEQ)          // 75648

#define CDIV(a,b) (((a)+(b)-1)/(b))

// ---------------- scratch (device globals: allocation-free) ----------------
static __device__ float g_x1 [TOK*EMB];
static __device__ float g_x2 [TOK*EMB];
static __device__ float g_xn [TOK*EMB];
static __device__ float g_qkv[TOK*EMB3];
static __device__ float g_S  [BH*SEQ*KW];
static __device__ float g_A  [BH*SEQ*KW];
static __device__ float g_y  [BH*KW*HD];
static __device__ float g_h  [TOK*HIDDEN];

// ---------------- elementwise ----------------
__global__ void init_copy(const float* __restrict__ x, float* __restrict__ x1,
                          float* __restrict__ x2, int n) {
    int i = blockIdx.x * blockDim.x + threadIdx.x;
    if (i < n) { float v = x[i]; x1[i] = v; x2[i] = v; }
}

__global__ void finalize_k(const float* __restrict__ x1, const float* __restrict__ x2,
                           float* __restrict__ out, int n) {
    int i = blockIdx.x * blockDim.x + threadIdx.x;
    if (i < n) out[i] = 0.5f * (x1[i] + x2[i]);
}

// ---------------- layernorm over rows of length 768 ----------------
__global__ void ln_row768(const float* __restrict__ x, const float* __restrict__ g,
                          const float* __restrict__ b, float* __restrict__ out) {
    int row = blockIdx.x;
    const float* xr = x + (size_t)row * EMB;
    float* orow = out + (size_t)row * EMB;
    int tid = threadIdx.x;  // 256
    float s = 0.f, ss = 0.f;
    for (int i = tid; i < EMB; i += 256) { float v = xr[i]; s += v; ss += v * v; }
    __shared__ float rs[8], rss[8];
    #pragma unroll
    for (int o = 16; o; o >>= 1) {
        s  += __shfl_xor_sync(0xffffffffu, s,  o);
        ss += __shfl_xor_sync(0xffffffffu, ss, o);
    }
    if ((tid & 31) == 0) { rs[tid >> 5] = s; rss[tid >> 5] = ss; }
    __syncthreads();
    if (tid < 32) {
        float a = (tid < 8) ? rs[tid]  : 0.f;
        float c = (tid < 8) ? rss[tid] : 0.f;
        #pragma unroll
        for (int o = 4; o; o >>= 1) {
            a += __shfl_xor_sync(0xffffffffu, a, o);
            c += __shfl_xor_sync(0xffffffffu, c, o);
        }
        if (tid == 0) { rs[0] = a; rss[0] = c; }
    }
    __syncthreads();
    float mu  = rs[0] * (1.0f / EMB);
    float var = rss[0] * (1.0f / EMB) - mu * mu;
    float inv = rsqrtf(var + 1e-5f);
    for (int i = tid; i < EMB; i += 256)
        orow[i] = (xr[i] - mu) * inv * g[i] + b[i];
}

// ---------------- big NN GEMM: C[M,N] = A[M,K] @ B[K,N], fused epilogues ----
// EPI: 0 none | 1 +bias | 2 +bias,gelu(exact) | 3 +bias,+res (residual add)
template <int EPI>
__global__ void __launch_bounds__(256) sgemm_nn(
    const float* __restrict__ A, const float* __restrict__ B,
    const float* __restrict__ bias, const float* __restrict__ res,
    float* __restrict__ C, int M, int Nn, int K)
{
    __shared__ float As[8][132];   // [k][m], pad 132 -> conflict-free STS & LDS
    __shared__ float Bs[8][128];   // [k][n]
    const int tid = threadIdx.x;
    const int tx = tid % 16, ty = tid / 16;
    const int m0 = blockIdx.y * 128, n0 = blockIdx.x * 128;
    float acc[8][8] = {};
    for (int k0 = 0; k0 < K; k0 += 8) {
        #pragma unroll
        for (int i = 0; i < 4; i++) {          // A tile 128x8
            int flat = tid + i * 256;
            int m = flat >> 3, k = flat & 7;
            int gm = m0 + m, gk = k0 + k;
            As[k][m] = (gm < M && gk < K) ? A[(size_t)gm * K + gk] : 0.f;
        }
        #pragma unroll
        for (int i = 0; i < 4; i++) {          // B tile 8x128
            int flat = tid + i * 256;
            int k = flat >> 7, n = flat & 127;
            int gk = k0 + k, gn = n0 + n;
            Bs[k][n] = (gk < K && gn < Nn) ? B[(size_t)gk * Nn + gn] : 0.f;
        }
        __syncthreads();
        #pragma unroll
        for (int kk = 0; kk < 8; kk++) {
            float a[8], bb[8];
            #pragma unroll
            for (int i = 0; i < 8; i++) a[i]  = As[kk][ty * 8 + i];
            #pragma unroll
            for (int j = 0; j < 8; j++) bb[j] = Bs[kk][tx * 8 + j];
            #pragma unroll
            for (int i = 0; i < 8; i++)
                #pragma unroll
                for (int j = 0; j < 8; j++)
                    acc[i][j] += a[i] * bb[j];
        }
        __syncthreads();
    }
    #pragma unroll
    for (int i = 0; i < 8; i++) {
        int gm = m0 + ty * 8 + i;
        if (gm >= M) continue;
        #pragma unroll
        for (int j = 0; j < 8; j++) {
            int gn = n0 + tx * 8 + j;
            if (gn >= Nn) continue;
            float v = acc[i][j];
            if (EPI >= 1) v += bias[gn];
            if (EPI == 2) v = 0.5f * v * (1.0f + erff(v * 0.70710678118654752f));
            if (EPI == 3) v += res[(size_t)gm * Nn + gn];
            C[(size_t)gm * Nn + gn] = v;
        }
    }
}

// ---------------- batched QK^T: S[z,n,m] = scale * sum_d q[n,d] k[m,d] ------
__global__ void __launch_bounds__(256) bgemm_qk(const float* __restrict__ qkv,
                                                float* __restrict__ S)
{
    __shared__ float Qs[64][65];
    __shared__ float Ks[64][65];
    const int z = blockIdx.z, b = z / HEADS, h = z % HEADS;
    const float* qb = qkv + (size_t)b * SEQ * EMB3 + h * HD;
    const float* kb = qb + EMB;
    const int n0 = blockIdx.y * 64, m0 = blockIdx.x * 64;
    const int tid = threadIdx.x, tx = tid % 16, ty = tid / 16;
    #pragma unroll
    for (int i = 0; i < 16; i++) {
        int flat = tid + i * 256;          // 0..4095
        int r = flat >> 6, c = flat & 63;
        int gn = n0 + r, gm = m0 + r;
        Qs[r][c] = (gn < SEQ) ? qb[(size_t)gn * EMB3 + c] : 0.f;
        Ks[r][c] = (gm < SEQ) ? kb[(size_t)gm * EMB3 + c] : 0.f;
    }
    __syncthreads();
    float acc[4][4] = {};
    #pragma unroll 8
    for (int kk = 0; kk < HD; kk++) {
        float a[4], bb[4];
        #pragma unroll
        for (int i = 0; i < 4; i++) a[i]  = Qs[ty * 4 + i][kk];
        #pragma unroll
        for (int j = 0; j < 4; j++) bb[j] = Ks[tx * 4 + j][kk];
        #pragma unroll
        for (int i = 0; i < 4; i++)
            #pragma unroll
            for (int j = 0; j < 4; j++)
                acc[i][j] += a[i] * bb[j];
    }
    const float scale = 0.125f;   // 64^-0.5
    #pragma unroll
    for (int i = 0; i < 4; i++) {
        int gn = n0 + ty * 4 + i;
        if (gn >= SEQ) continue;
        #pragma unroll
        for (int j = 0; j < 4; j++) {
            int gm = m0 + tx * 4 + j;
            if (gm >= SEQ) continue;
            S[(size_t)z * SEQ * KW + (size_t)gn * KW + gm] = acc[i][j] * scale;
        }
    }
}

// ---------------- fused LN(KW) + softmax(KW), warp per row -----------------
__global__ void ln_softmax(float* __restrict__ A, const float* __restrict__ g,
                           const float* __restrict__ bb)
{
    int warp = (blockIdx.x * blockDim.x + threadIdx.x) >> 5;
    int lane = threadIdx.x & 31;
    if (warp >= ROWSA) return;
    float* row = A + (size_t)warp * KW;
    float v[7];
    float s = 0.f, ss = 0.f;
    #pragma unroll
    for (int i = 0; i < 7; i++) {
        int idx = lane + i * 32;
        v[i] = (idx < KW) ? row[idx] : 0.f;
        s += v[i]; ss += v[i] * v[i];
    }
    #pragma unroll
    for (int o = 16; o; o >>= 1) {
        s  += __shfl_xor_sync(0xffffffffu, s,  o);
        ss += __shfl_xor_sync(0xffffffffu, ss, o);
    }
    float mu  = s * (1.0f / KW);
    float var = ss * (1.0f / KW) - mu * mu;
    float inv = rsqrtf(var + 1e-5f);
    float mx = -1e30f;
    #pragma unroll
    for (int i = 0; i < 7; i++) {
        int idx = lane + i * 32;
        if (idx < KW) {
            float zv = (v[i] - mu) * inv * g[idx] + bb[idx];
            v[i] = zv;
            mx = fmaxf(mx, zv);
        } else v[i] = -1e30f;
    }
    #pragma unroll
    for (int o = 16; o; o >>= 1) mx = fmaxf(mx, __shfl_xor_sync(0xffffffffu, mx, o));
    float se = 0.f;
    #pragma unroll
    for (int i = 0; i < 7; i++) {
        int idx = lane + i * 32;
        float e = (idx < KW) ? __expf(v[i] - mx) : 0.f;
        v[i] = e; se += e;
    }
    #pragma unroll
    for (int o = 16; o; o >>= 1) se += __shfl_xor_sync(0xffffffffu, se, o);
    float r = 1.0f / se;
    #pragma unroll
    for (int i = 0; i < 7; i++) {
        int idx = lane + i * 32;
        if (idx < KW) row[idx] = v[i] * r;
    }
}

// ---------------- batched P^T V: y[z,k,d] = sum_n P[z,n,k] v[z,n,d] --------
__global__ void __launch_bounds__(256) bgemm_pv(const float* __restrict__ P,
                                                const float* __restrict__ qkv,
                                                float* __restrict__ y)
{
    __shared__ float As[16][65];  // [kred][m]  (m = output k index over KW)
    __shared__ float Bs[16][65];  // [kred][n]  (n = head dim)
    const int z = blockIdx.z, b = z / HEADS, h = z % HEADS;
    const float* Ab = P + (size_t)z * SEQ * KW;
    const float* Bb = qkv + (size_t)b * SEQ * EMB3 + h * HD + 2 * EMB;
    const int m0 = blockIdx.y * 64;
    const int tid = threadIdx.x, tx = tid % 16, ty = tid / 16;
    float acc[4][4] = {};
    for (int k0 = 0; k0 < SEQ; k0 += 16) {
        #pragma unroll
        for (int i = 0; i < 4; i++) {
            int flat = tid + i * 256;
            int k = flat >> 6, m = flat & 63;
            int gk = k0 + k;
            As[k][m] = (gk < SEQ && (m0 + m) < KW) ? Ab[(size_t)gk * KW + m0 + m] : 0.f;
            Bs[k][m] = (gk < SEQ) ? Bb[(size_t)gk * EMB3 + m] : 0.f;
        }
        __syncthreads();
        #pragma unroll
        for (int kk = 0; kk < 16; kk++) {
            float a[4], bb[4];
            #pragma unroll
            for (int i = 0; i < 4; i++) a[i]  = As[kk][ty * 4 + i];
            #pragma unroll
            for (int j = 0; j < 4; j++) bb[j] = Bs[kk][tx * 4 + j];
            #pragma unroll
            for (int i = 0; i < 4; i++)
                #pragma unroll
                for (int j = 0; j < 4; j++)
                    acc[i][j] += a[i] * bb[j];
        }
        __syncthreads();
    }
    #pragma unroll
    for (int i = 0; i < 4; i++) {
        int gm = m0 + ty * 4 + i;
        if (gm >= KW) continue;
        #pragma unroll
        for (int j = 0; j < 4; j++) {
            int gn = tx * 4 + j;   // < 64 always
            y[(size_t)z * KW * HD + (size_t)gm * HD + gn] = acc[i][j];
        }
    }
}

// -------- batched fc2: x1[b,n,h,d] += sum_k fc2_w[k,n] y[z,k,d] + fc2_b[n] --
__global__ void __launch_bounds__(256) bgemm_out(const float* __restrict__ W,
                                                 const float* __restrict__ y,
                                                 const float* __restrict__ bias,
                                                 float* __restrict__ x1)
{
    __shared__ float As[16][65];  // [k][m]  (m = token index n)
    __shared__ float Bs[16][65];  // [k][n]  (n = head dim)
    const int z = blockIdx.z, b = z / HEADS, h = z % HEADS;
    const float* Bb = y + (size_t)z * KW * HD;
    const int m0 = blockIdx.y * 64;
    const int tid = threadIdx.x, tx = tid % 16, ty = tid / 16;
    float acc[4][4] = {};
    for (int k0 = 0; k0 < KW; k0 += 16) {
        #pragma unroll
        for (int i = 0; i < 4; i++) {
            int flat = tid + i * 256;
            int k = flat >> 6, m = flat & 63;
            int gk = k0 + k;
            As[k][m] = (gk < KW && (m0 + m) < SEQ) ? W[(size_t)gk * SEQ + m0 + m] : 0.f;
            Bs[k][m] = (gk < KW) ? Bb[(size_t)gk * HD + m] : 0.f;
        }
        __syncthreads();
        #pragma unroll
        for (int kk = 0; kk < 16; kk++) {
            float a[4], bb[4];
            #pragma unroll
            for (int i = 0; i < 4; i++) a[i]  = As[kk][ty * 4 + i];
            #pragma unroll
            for (int j = 0; j < 4; j++) bb[j] = Bs[kk][tx * 4 + j];
            #pragma unroll
            for (int i = 0; i < 4; i++)
                #pragma unroll
                for (int j = 0; j < 4; j++)
                    acc[i][j] += a[i] * bb[j];
        }
        __syncthreads();
    }
    #pragma unroll
    for (int i = 0; i < 4; i++) {
        int gm = m0 + ty * 4 + i;       // token index
        if (gm >= SEQ) continue;
        #pragma unroll
        for (int j = 0; j < 4; j++) {
            int gn = tx * 4 + j;        // head dim, < 64 always
            float v = acc[i][j] + bias[gm];
            size_t idx = ((size_t)(b * SEQ + gm)) * EMB + h * HD + gn;
            x1[idx] += v;
        }
    }
}

// ---------------- launch ----------------
extern "C" void kernel_launch(void* const* d_in, const int* in_sizes, int n_in,
                              void* d_out, int out_size) {
    (void)in_sizes; (void)n_in; (void)out_size;
    const float* x         = (const float*)d_in[0];
    const float* qkv_w     = (const float*)d_in[1];
    const float* fc_w      = (const float*)d_in[2];
    const float* fc_b      = (const float*)d_in[3];
    const float* attn_ln_g = (const float*)d_in[4];
    const float* attn_ln_b = (const float*)d_in[5];
    const float* fc2_w     = (const float*)d_in[6];
    const float* fc2_b     = (const float*)d_in[7];
    const float* mlp_w1    = (const float*)d_in[8];
    const float* mlp_b1    = (const float*)d_in[9];
    const float* mlp_w2    = (const float*)d_in[10];
    const float* mlp_b2    = (const float*)d_in[11];
    const float* f_ln_g    = (const float*)d_in[12];
    const float* f_ln_b    = (const float*)d_in[13];
    const float* gl_ln_g   = (const float*)d_in[14];
    const float* gl_ln_b   = (const float*)d_in[15];

    float *px1, *px2, *pxn, *pqkv, *pS, *pA, *py, *ph;
    cudaGetSymbolAddress((void**)&px1,  g_x1);
    cudaGetSymbolAddress((void**)&px2,  g_x2);
    cudaGetSymbolAddress((void**)&pxn,  g_xn);
    cudaGetSymbolAddress((void**)&pqkv, g_qkv);
    cudaGetSymbolAddress((void**)&pS,   g_S);
    cudaGetSymbolAddress((void**)&pA,   g_A);
    cudaGetSymbolAddress((void**)&py,   g_y);
    cudaGetSymbolAddress((void**)&ph,   g_h);

    const int NE = TOK * EMB;
    init_copy<<<CDIV(NE, 256), 256>>>(x, px1, px2, NE);

    for (int l = 0; l < NLAYERS; ++l) {
        // y1 = x1 + attention(LN_f(x2))
        ln_row768<<<TOK, 256>>>(px2, f_ln_g + l * EMB, f_ln_b + l * EMB, pxn);
        sgemm_nn<0><<<dim3(CDIV(EMB3, 128), CDIV(TOK, 128)), 256>>>(
            pxn, qkv_w, nullptr, nullptr, pqkv, TOK, EMB3, EMB);
        bgemm_qk<<<dim3(4, 4, BH), 256>>>(pqkv, pS);
        sgemm_nn<1><<<dim3(CDIV(KW, 128), CDIV(ROWSA, 128)), 256>>>(
            pS, fc_w, fc_b, nullptr, pA, ROWSA, KW, SEQ);
        ln_softmax<<<ROWSA / 8, 256>>>(pA, attn_ln_g, attn_ln_b);
        bgemm_pv<<<dim3(1, 4, BH), 256>>>(pA, pqkv, py);
        bgemm_out<<<dim3(1, 4, BH), 256>>>(fc2_w, py, fc2_b, px1);   // x1 += attn_out
        // y2 = x2 + mlp(LN_g(y1))
        ln_row768<<<TOK, 256>>>(px1, gl_ln_g + l * EMB, gl_ln_b + l * EMB, pxn);
        sgemm_nn<2><<<dim3(CDIV(HIDDEN, 128), CDIV(TOK, 128)), 256>>>(
            pxn, mlp_w1, mlp_b1, nullptr, ph, TOK, HIDDEN, EMB);
        sgemm_nn<3><<<dim3(CDIV(EMB, 128), CDIV(TOK, 128)), 256>>>(
            ph, mlp_w2, mlp_b2, px2, px2, TOK, EMB, HIDDEN);         // x2 += mlp_out
    }

    finalize_k<<<CDIV(NE, 256), 256>>>(px1, px2, (float*)d_out, NE);
}

// round 2
// speedup vs baseline: 2.9701x; 2.9701x over previous
#include <cuda_runtime.h>
#include <math.h>
#include <stdint.h>

#define BATCH   32
#define SEQ     197
#define EMB     768
#define EMB3    2304
#define HEADS   12
#define HD      64
#define KW      197
#define NLAYERS 12
#define HIDDEN  3072
#define TOK     (BATCH*SEQ)       // 6304
#define BH      (BATCH*HEADS)     // 384
#define ROWSA   (BH*SEQ)          // 75648
#define SPAD    224               // padded KW stride for S (16B aligned, mult of 32)
#define FCNPAD  208               // padded N stride for fc_w (16B aligned)

#define CDIV(a,b) (((a)+(b)-1)/(b))

// ---------------- scratch (device globals: allocation-free) ----------------
static __device__ float g_x1 [TOK*EMB];
static __device__ float g_x2 [TOK*EMB];
static __device__ float g_xn [TOK*EMB];
static __device__ float g_qkv[TOK*EMB3];
static __device__ float g_S  [(size_t)BH*SEQ*SPAD];
static __device__ float g_A  [(size_t)BH*SEQ*KW];
static __device__ float g_y  [BH*KW*HD];
static __device__ float g_h  [TOK*HIDDEN];
// tf32-rounded weight copies
static __device__ float g_wqkv[EMB*EMB3];
static __device__ float g_wfc [SPAD*FCNPAD];
static __device__ float g_w1  [EMB*HIDDEN];
static __device__ float g_w2  [HIDDEN*EMB];

// ---------------- helpers ----------------
__device__ __forceinline__ uint32_t f2tf_u(float x) {
    uint32_t r; asm("cvt.rna.tf32.f32 %0, %1;" : "=r"(r) : "f"(x)); return r;
}
__device__ __forceinline__ float f2tf_f(float x) { return __uint_as_float(f2tf_u(x)); }

__device__ __forceinline__ void cpasync16(uint32_t dst, const void* src, int srcbytes) {
    asm volatile("cp.async.cg.shared.global [%0], [%1], 16, %2;\n"
                 :: "r"(dst), "l"(src), "r"(srcbytes));
}
__device__ __forceinline__ void cp_commit() { asm volatile("cp.async.commit_group;\n"); }

// ---------------- elementwise ----------------
__global__ void init_copy(const float* __restrict__ x, float* __restrict__ x1,
                          float* __restrict__ x2, int n) {
    int i = blockIdx.x * blockDim.x + threadIdx.x;
    if (i < n) { float v = x[i]; x1[i] = v; x2[i] = v; }
}

__global__ void finalize_k(const float* __restrict__ x1, const float* __restrict__ x2,
                           float* __restrict__ out, int n) {
    int i = blockIdx.x * blockDim.x + threadIdx.x;
    if (i < n) out[i] = 0.5f * (x1[i] + x2[i]);
}

__global__ void prep_round(const float* __restrict__ s, float* __restrict__ d, int n) {
    int i = blockIdx.x * blockDim.x + threadIdx.x;
    if (i < n) d[i] = f2tf_f(s[i]);
}

__global__ void prep_fc(const float* __restrict__ s, float* __restrict__ d) {
    int i = blockIdx.x * blockDim.x + threadIdx.x;
    if (i < SPAD * FCNPAD) {
        int k = i / FCNPAD, n = i % FCNPAD;
        d[i] = (k < KW && n < SEQ) ? f2tf_f(s[k * SEQ + n]) : 0.f;
    }
}

__global__ void zero_pad_S(float* __restrict__ S) {
    int i = blockIdx.x * blockDim.x + threadIdx.x;
    const int padw = SPAD - KW;                 // 27
    if (i < ROWSA * padw) {
        int r = i / padw, c = KW + i % padw;
        S[(size_t)r * SPAD + c] = 0.f;
    }
}

// ---------------- layernorm over rows of length 768 (tf32-rounded out) -----
__global__ void ln_row768(const float* __restrict__ x, const float* __restrict__ g,
                          const float* __restrict__ b, float* __restrict__ out) {
    int row = blockIdx.x;
    const float* xr = x + (size_t)row * EMB;
    float* orow = out + (size_t)row * EMB;
    int tid = threadIdx.x;  // 256
    float s = 0.f, ss = 0.f;
    for (int i = tid; i < EMB; i += 256) { float v = xr[i]; s += v; ss += v * v; }
    __shared__ float rs[8], rss[8];
    #pragma unroll
    for (int o = 16; o; o >>= 1) {
        s  += __shfl_xor_sync(0xffffffffu, s,  o);
        ss += __shfl_xor_sync(0xffffffffu, ss, o);
    }
    if ((tid & 31) == 0) { rs[tid >> 5] = s; rss[tid >> 5] = ss; }
    __syncthreads();
    if (tid < 32) {
        float a = (tid < 8) ? rs[tid]  : 0.f;
        float c = (tid < 8) ? rss[tid] : 0.f;
        #pragma unroll
        for (int o = 4; o; o >>= 1) {
            a += __shfl_xor_sync(0xffffffffu, a, o);
            c += __shfl_xor_sync(0xffffffffu, c, o);
        }
        if (tid == 0) { rs[0] = a; rss[0] = c; }
    }
    __syncthreads();
    float mu  = rs[0] * (1.0f / EMB);
    float var = rss[0] * (1.0f / EMB) - mu * mu;
    float inv = rsqrtf(var + 1e-5f);
    for (int i = tid; i < EMB; i += 256)
        orow[i] = f2tf_f((xr[i] - mu) * inv * g[i] + b[i]);
}

// ================= tf32 tensor-core GEMM =================
// C[M,N] = A[M,K] @ B[K,ldb..N], A stride = K (mult of 32, 16B-aligned rows),
// B stride = ldb. Block tile 128x128, 8 warps (2x4) of 64x32, k-chunk 16,
// cp.async double-buffered.
// EPI: 0 none | 1 +bias | 2 +bias,gelu,rna | 3 +bias,+res
#define KCH 16
#define AS_STRIDE 20     // (20 mod 32)=20; frag addr 20m+k conflict-free
#define BS_STRIDE 136    // (136 mod 32)=8; frag addr 8k+n conflict-free
#define AS_STAGE (128*AS_STRIDE)   // 2560 floats
#define BS_STAGE (KCH*BS_STRIDE)   // 2176 floats

template <int EPI>
__global__ void __launch_bounds__(256) gemm_tf32(
    const float* __restrict__ A, const float* __restrict__ B, int ldb,
    const float* __restrict__ bias, const float* __restrict__ res,
    float* __restrict__ C, int M, int N, int K)
{
    __shared__ float As[2 * AS_STAGE];
    __shared__ float Bs[2 * BS_STAGE];
    const int tid  = threadIdx.x;
    const int warp = tid >> 5, lane = tid & 31;
    const int wm = warp >> 2, wn = warp & 3;   // 2 x 4 warp grid
    const int g = lane >> 2, t = lane & 3;
    const int m0 = blockIdx.y * 128, n0 = blockIdx.x * 128;

    const uint32_t as_u = (uint32_t)__cvta_generic_to_shared(As);
    const uint32_t bs_u = (uint32_t)__cvta_generic_to_shared(Bs);

    // per-thread cp.async coordinates
    // A: 128 rows x 16 floats -> 512 x 16B -> 2 per thread
    const int am0 = tid >> 2,       aseg = (tid & 3) * 4;       // i=0
    const int am1 = (tid + 256) >> 2;                            // i=1, same aseg
    // B: 16 rows x 128 floats -> 512 x 16B -> 2 per thread
    const int bk0 = tid >> 5,       bseg = (tid & 31) * 4;       // i=0
    const int bk1 = (tid + 256) >> 5;                            // i=1, same bseg

    float acc[4][4][4];
    #pragma unroll
    for (int i = 0; i < 4; i++)
        #pragma unroll
        for (int j = 0; j < 4; j++)
            #pragma unroll
            for (int r = 0; r < 4; r++) acc[i][j][r] = 0.f;

    const int nch = K / KCH;

    // prefetch chunk 0 into stage 0
    {
        const int k0 = 0;
        cpasync16(as_u + (size_t)(am0 * AS_STRIDE + aseg) * 4,
                  A + (size_t)(m0 + am0) * K + k0 + aseg, (m0 + am0 < M) ? 16 : 0);
        cpasync16(as_u + (size_t)(am1 * AS_STRIDE + aseg) * 4,
                  A + (size_t)(m0 + am1) * K + k0 + aseg, (m0 + am1 < M) ? 16 : 0);
        cpasync16(bs_u + (size_t)(bk0 * BS_STRIDE + bseg) * 4,
                  B + (size_t)(k0 + bk0) * ldb + n0 + bseg, (n0 + bseg < ldb) ? 16 : 0);
        cpasync16(bs_u + (size_t)(bk1 * BS_STRIDE + bseg) * 4,
                  B + (size_t)(k0 + bk1) * ldb + n0 + bseg, (n0 + bseg < ldb) ? 16 : 0);
        cp_commit();
    }

    for (int c = 0; c < nch; ++c) {
        if (c + 1 < nch) {
            const int k0 = (c + 1) * KCH;
            const int st = ((c + 1) & 1);
            cpasync16(as_u + (size_t)(st * AS_STAGE + am0 * AS_STRIDE + aseg) * 4,
                      A + (size_t)(m0 + am0) * K + k0 + aseg, (m0 + am0 < M) ? 16 : 0);
            cpasync16(as_u + (size_t)(st * AS_STAGE + am1 * AS_STRIDE + aseg) * 4,
                      A + (size_t)(m0 + am1) * K + k0 + aseg, (m0 + am1 < M) ? 16 : 0);
            cpasync16(bs_u + (size_t)(st * BS_STAGE + bk0 * BS_STRIDE + bseg) * 4,
                      B + (size_t)(k0 + bk0) * ldb + n0 + bseg, (n0 + bseg < ldb) ? 16 : 0);
            cpasync16(bs_u + (size_t)(st * BS_STAGE + bk1 * BS_STRIDE + bseg) * 4,
                      B + (size_t)(k0 + bk1) * ldb + n0 + bseg, (n0 + bseg < ldb) ? 16 : 0);
            cp_commit();
            asm volatile("cp.async.wait_group 1;\n");
        } else {
            asm volatile("cp.async.wait_group 0;\n");
        }
        __syncthreads();

        const uint32_t* as = (const uint32_t*)(As + (c & 1) * AS_STAGE);
        const uint32_t* bs = (const uint32_t*)(Bs + (c & 1) * BS_STAGE);

        #pragma unroll
        for (int kk = 0; kk < KCH / 8; ++kk) {
            const int kb = kk * 8;
            uint32_t afr[4][4];
            uint32_t bfr[4][2];
            #pragma unroll
            for (int mi = 0; mi < 4; mi++) {
                int m = wm * 64 + mi * 16 + g;
                afr[mi][0] = as[(m    ) * AS_STRIDE + kb + t    ];
                afr[mi][1] = as[(m + 8) * AS_STRIDE + kb + t    ];
                afr[mi][2] = as[(m    ) * AS_STRIDE + kb + t + 4];
                afr[mi][3] = as[(m + 8) * AS_STRIDE + kb + t + 4];
            }
            #pragma unroll
            for (int nj = 0; nj < 4; nj++) {
                int n = wn * 32 + nj * 8 + g;
                bfr[nj][0] = bs[(kb + t    ) * BS_STRIDE + n];
                bfr[nj][1] = bs[(kb + t + 4) * BS_STRIDE + n];
            }
            #pragma unroll
            for (int mi = 0; mi < 4; mi++)
                #pragma unroll
                for (int nj = 0; nj < 4; nj++) {
                    asm volatile(
                        "mma.sync.aligned.m16n8k8.row.col.f32.tf32.tf32.f32 "
                        "{%0,%1,%2,%3}, {%4,%5,%6,%7}, {%8,%9}, {%0,%1,%2,%3};\n"
                        : "+f"(acc[mi][nj][0]), "+f"(acc[mi][nj][1]),
                          "+f"(acc[mi][nj][2]), "+f"(acc[mi][nj][3])
                        : "r"(afr[mi][0]), "r"(afr[mi][1]),
                          "r"(afr[mi][2]), "r"(afr[mi][3]),
                          "r"(bfr[nj][0]), "r"(bfr[nj][1]));
                }
        }
        __syncthreads();
    }

    // epilogue
    #pragma unroll
    for (int mi = 0; mi < 4; mi++) {
        int r0 = m0 + wm * 64 + mi * 16 + g;
        #pragma unroll
        for (int nj = 0; nj < 4; nj++) {
            int cb = n0 + wn * 32 + nj * 8 + 2 * t;
            #pragma unroll
            for (int half = 0; half < 2; half++) {
                int gm = r0 + half * 8;
                if (gm >= M) continue;
                #pragma unroll
                for (int q = 0; q < 2; q++) {
                    int gn = cb + q;
                    if (gn >= N) continue;
                    float v = acc[mi][nj][half * 2 + q];
                    if (EPI >= 1) v += bias[gn];
                    if (EPI == 2) {
                        v = 0.5f * v * (1.0f + erff(v * 0.70710678118654752f));
                        v = f2tf_f(v);   // feeds next tf32 GEMM
                    }
                    if (EPI == 3) v += res[(size_t)gm * N + gn];
                    C[(size_t)gm * N + gn] = v;
                }
            }
        }
    }
}

// ---------------- batched QK^T (fp32): S padded stride, tf32-rounded out ---
__global__ void __launch_bounds__(256) bgemm_qk(const float* __restrict__ qkv,
                                                float* __restrict__ S)
{
    __shared__ float Qs[64][65];
    __shared__ float Ks[64][65];
    const int z = blockIdx.z, b = z / HEADS, h = z % HEADS;
    const float* qb = qkv + (size_t)b * SEQ * EMB3 + h * HD;
    const float* kb = qb + EMB;
    const int n0 = blockIdx.y * 64, m0 = blockIdx.x * 64;
    const int tid = threadIdx.x, tx = tid % 16, ty = tid / 16;
    #pragma unroll
    for (int i = 0; i < 16; i++) {
        int flat = tid + i * 256;
        int r = flat >> 6, c = flat & 63;
        int gn = n0 + r, gm = m0 + r;
        Qs[r][c] = (gn < SEQ) ? qb[(size_t)gn * EMB3 + c] : 0.f;
        Ks[r][c] = (gm < SEQ) ? kb[(size_t)gm * EMB3 + c] : 0.f;
    }
    __syncthreads();
    float acc[4][4] = {};
    #pragma unroll 8
    for (int kk = 0; kk < HD; kk++) {
        float a[4], bb[4];
        #pragma unroll
        for (int i = 0; i < 4; i++) a[i]  = Qs[ty * 4 + i][kk];
        #pragma unroll
        for (int j = 0; j < 4; j++) bb[j] = Ks[tx * 4 + j][kk];
        #pragma unroll
        for (int i = 0; i < 4; i++)
            #pragma unroll
            for (int j = 0; j < 4; j++)
                acc[i][j] += a[i] * bb[j];
    }
    const float scale = 0.125f;
    #pragma unroll
    for (int i = 0; i < 4; i++) {
        int gn = n0 + ty * 4 + i;
        if (gn >= SEQ) continue;
        #pragma unroll
        for (int j = 0; j < 4; j++) {
            int gm = m0 + tx * 4 + j;
            if (gm >= SEQ) continue;
            S[(size_t)z * SEQ * SPAD + (size_t)gn * SPAD + gm] = f2tf_f(acc[i][j] * scale);
        }
    }
}

// ---------------- fused LN(KW) + softmax(KW), warp per row -----------------
__global__ void ln_softmax(float* __restrict__ A, const float* __restrict__ g,
                           const float* __restrict__ bb)
{
    int warp = (blockIdx.x * blockDim.x + threadIdx.x) >> 5;
    int lane = threadIdx.x & 31;
    if (warp >= ROWSA) return;
    float* row = A + (size_t)warp * KW;
    float v[7];
    float s = 0.f, ss = 0.f;
    #pragma unroll
    for (int i = 0; i < 7; i++) {
        int idx = lane + i * 32;
        v[i] = (idx < KW) ? row[idx] : 0.f;
        s += v[i]; ss += v[i] * v[i];
    }
    #pragma unroll
    for (int o = 16; o; o >>= 1) {
        s  += __shfl_xor_sync(0xffffffffu, s,  o);
        ss += __shfl_xor_sync(0xffffffffu, ss, o);
    }
    float mu  = s * (1.0f / KW);
    float var = ss * (1.0f / KW) - mu * mu;
    float inv = rsqrtf(var + 1e-5f);
    float mx = -1e30f;
    #pragma unroll
    for (int i = 0; i < 7; i++) {
        int idx = lane + i * 32;
        if (idx < KW) {
            float zv = (v[i] - mu) * inv * g[idx] + bb[idx];
            v[i] = zv;
            mx = fmaxf(mx, zv);
        } else v[i] = -1e30f;
    }
    #pragma unroll
    for (int o = 16; o; o >>= 1) mx = fmaxf(mx, __shfl_xor_sync(0xffffffffu, mx, o));
    float se = 0.f;
    #pragma unroll
    for (int i = 0; i < 7; i++) {
        int idx = lane + i * 32;
        float e = (idx < KW) ? __expf(v[i] - mx) : 0.f;
        v[i] = e; se += e;
    }
    #pragma unroll
    for (int o = 16; o; o >>= 1) se += __shfl_xor_sync(0xffffffffu, se, o);
    float r = 1.0f / se;
    #pragma unroll
    for (int i = 0; i < 7; i++) {
        int idx = lane + i * 32;
        if (idx < KW) row[idx] = v[i] * r;
    }
}

// ---------------- batched P^T V (fp32) --------------------------------------
__global__ void __launch_bounds__(256) bgemm_pv(const float* __restrict__ P,
                                                const float* __restrict__ qkv,
                                                float* __restrict__ y)
{
    __shared__ float As[16][65];
    __shared__ float Bs[16][65];
    const int z = blockIdx.z, b = z / HEADS, h = z % HEADS;
    const float* Ab = P + (size_t)z * SEQ * KW;
    const float* Bb = qkv + (size_t)b * SEQ * EMB3 + h * HD + 2 * EMB;
    const int m0 = blockIdx.y * 64;
    const int tid = threadIdx.x, tx = tid % 16, ty = tid / 16;
    float acc[4][4] = {};
    for (int k0 = 0; k0 < SEQ; k0 += 16) {
        #pragma unroll
        for (int i = 0; i < 4; i++) {
            int flat = tid + i * 256;
            int k = flat >> 6, m = flat & 63;
            int gk = k0 + k;
            As[k][m] = (gk < SEQ && (m0 + m) < KW) ? Ab[(size_t)gk * KW + m0 + m] : 0.f;
            Bs[k][m] = (gk < SEQ) ? Bb[(size_t)gk * EMB3 + m] : 0.f;
        }
        __syncthreads();
        #pragma unroll
        for (int kk = 0; kk < 16; kk++) {
            float a[4], bb[4];
            #pragma unroll
            for (int i = 0; i < 4; i++) a[i]  = As[kk][ty * 4 + i];
            #pragma unroll
            for (int j = 0; j < 4; j++) bb[j] = Bs[kk][tx * 4 + j];
            #pragma unroll
            for (int i = 0; i < 4; i++)
                #pragma unroll
                for (int j = 0; j < 4; j++)
                    acc[i][j] += a[i] * bb[j];
        }
        __syncthreads();
    }
    #pragma unroll
    for (int i = 0; i < 4; i++) {
        int gm = m0 + ty * 4 + i;
        if (gm >= KW) continue;
        #pragma unroll
        for (int j = 0; j < 4; j++) {
            int gn = tx * 4 + j;
            y[(size_t)z * KW * HD + (size_t)gm * HD + gn] = acc[i][j];
        }
    }
}

// -------- batched fc2: x1 += einsum + bias (fp32) --------------------------
__global__ void __launch_bounds__(256) bgemm_out(const float* __restrict__ W,
                                                 const float* __restrict__ y,
                                                 const float* __restrict__ bias,
                                                 float* __restrict__ x1)
{
    __shared__ float As[16][65];
    __shared__ float Bs[16][65];
    const int z = blockIdx.z, b = z / HEADS, h = z % HEADS;
    const float* Bb = y + (size_t)z * KW * HD;
    const int m0 = blockIdx.y * 64;
    const int tid = threadIdx.x, tx = tid % 16, ty = tid / 16;
    float acc[4][4] = {};
    for (int k0 = 0; k0 < KW; k0 += 16) {
        #pragma unroll
        for (int i = 0; i < 4; i++) {
            int flat = tid + i * 256;
            int k = flat >> 6, m = flat & 63;
            int gk = k0 + k;
            As[k][m] = (gk < KW && (m0 + m) < SEQ) ? W[(size_t)gk * SEQ + m0 + m] : 0.f;
            Bs[k][m] = (gk < KW) ? Bb[(size_t)gk * HD + m] : 0.f;
        }
        __syncthreads();
        #pragma unroll
        for (int kk = 0; kk < 16; kk++) {
            float a[4], bb[4];
            #pragma unroll
            for (int i = 0; i < 4; i++) a[i]  = As[kk][ty * 4 + i];
            #pragma unroll
            for (int j = 0; j < 4; j++) bb[j] = Bs[kk][tx * 4 + j];
            #pragma unroll
            for (int i = 0; i < 4; i++)
                #pragma unroll
                for (int j = 0; j < 4; j++)
                    acc[i][j] += a[i] * bb[j];
        }
        __syncthreads();
    }
    #pragma unroll
    for (int i = 0; i < 4; i++) {
        int gm = m0 + ty * 4 + i;
        if (gm >= SEQ) continue;
        #pragma unroll
        for (int j = 0; j < 4; j++) {
            int gn = tx * 4 + j;
            float v = acc[i][j] + bias[gm];
            size_t idx = ((size_t)(b * SEQ + gm)) * EMB + h * HD + gn;
            x1[idx] += v;
        }
    }
}

// ---------------- launch ----------------
extern "C" void kernel_launch(void* const* d_in, const int* in_sizes, int n_in,
                              void* d_out, int out_size) {
    (void)in_sizes; (void)n_in; (void)out_size;
    const float* x         = (const float*)d_in[0];
    const float* qkv_w     = (const float*)d_in[1];
    const float* fc_w      = (const float*)d_in[2];
    const float* fc_b      = (const float*)d_in[3];
    const float* attn_ln_g = (const float*)d_in[4];
    const float* attn_ln_b = (const float*)d_in[5];
    const float* fc2_w     = (const float*)d_in[6];
    const float* fc2_b     = (const float*)d_in[7];
    const float* mlp_w1    = (const float*)d_in[8];
    const float* mlp_b1    = (const float*)d_in[9];
    const float* mlp_w2    = (const float*)d_in[10];
    const float* mlp_b2    = (const float*)d_in[11];
    const float* f_ln_g    = (const float*)d_in[12];
    const float* f_ln_b    = (const float*)d_in[13];
    const float* gl_ln_g   = (const float*)d_in[14];
    const float* gl_ln_b   = (const float*)d_in[15];

    float *px1, *px2, *pxn, *pqkv, *pS, *pA, *py, *ph;
    float *pwqkv, *pwfc, *pw1, *pw2;
    cudaGetSymbolAddress((void**)&px1,  g_x1);
    cudaGetSymbolAddress((void**)&px2,  g_x2);
    cudaGetSymbolAddress((void**)&pxn,  g_xn);
    cudaGetSymbolAddress((void**)&pqkv, g_qkv);
    cudaGetSymbolAddress((void**)&pS,   g_S);
    cudaGetSymbolAddress((void**)&pA,   g_A);
    cudaGetSymbolAddress((void**)&py,   g_y);
    cudaGetSymbolAddress((void**)&ph,   g_h);
    cudaGetSymbolAddress((void**)&pwqkv, g_wqkv);
    cudaGetSymbolAddress((void**)&pwfc,  g_wfc);
    cudaGetSymbolAddress((void**)&pw1,   g_w1);
    cudaGetSymbolAddress((void**)&pw2,   g_w2);

    const int NE = TOK * EMB;

    // one-time (per launch) weight prep + S padding zero
    prep_round<<<CDIV(EMB*EMB3, 256), 256>>>(qkv_w, pwqkv, EMB*EMB3);
    prep_round<<<CDIV(EMB*HIDDEN, 256), 256>>>(mlp_w1, pw1, EMB*HIDDEN);
    prep_round<<<CDIV(HIDDEN*EMB, 256), 256>>>(mlp_w2, pw2, HIDDEN*EMB);
    prep_fc<<<CDIV(SPAD*FCNPAD, 256), 256>>>(fc_w, pwfc);
    zero_pad_S<<<CDIV(ROWSA*(SPAD-KW), 256), 256>>>(pS);

    init_copy<<<CDIV(NE, 256), 256>>>(x, px1, px2, NE);

    for (int l = 0; l < NLAYERS; ++l) {
        // y1 = x1 + attention(LN_f(x2))
        ln_row768<<<TOK, 256>>>(px2, f_ln_g + l * EMB, f_ln_b + l * EMB, pxn);
        gemm_tf32<0><<<dim3(CDIV(EMB3, 128), CDIV(TOK, 128)), 256>>>(
            pxn, pwqkv, EMB3, nullptr, nullptr, pqkv, TOK, EMB3, EMB);
        bgemm_qk<<<dim3(4, 4, BH), 256>>>(pqkv, pS);
        gemm_tf32<1><<<dim3(CDIV(KW, 128), CDIV(ROWSA, 128)), 256>>>(
            pS, pwfc, FCNPAD, fc_b, nullptr, pA, ROWSA, KW, SPAD);
        ln_softmax<<<ROWSA / 8, 256>>>(pA, attn_ln_g, attn_ln_b);
        bgemm_pv<<<dim3(1, 4, BH), 256>>>(pA, pqkv, py);
        bgemm_out<<<dim3(1, 4, BH), 256>>>(fc2_w, py, fc2_b, px1);   // x1 += attn_out
        // y2 = x2 + mlp(LN_g(y1))
        ln_row768<<<TOK, 256>>>(px1, gl_ln_g + l * EMB, gl_ln_b + l * EMB, pxn);
        gemm_tf32<2><<<dim3(CDIV(HIDDEN, 128), CDIV(TOK, 128)), 256>>>(
            pxn, pw1, HIDDEN, mlp_b1, nullptr, ph, TOK, HIDDEN, EMB);
        gemm_tf32<3><<<dim3(CDIV(EMB, 128), CDIV(TOK, 128)), 256>>>(
            ph, pw2, EMB, mlp_b2, px2, px2, TOK, EMB, HIDDEN);       // x2 += mlp_out
    }

    finalize_k<<<CDIV(NE, 256), 256>>>(px1, px2, (float*)d_out, NE);
}

// round 3
// speedup vs baseline: 3.5960x; 1.2108x over previous
#include <cuda_runtime.h>
#include <math.h>
#include <stdint.h>

#define BATCH   32
#define SEQ     197
#define EMB     768
#define EMB3    2304
#define HEADS   12
#define HD      64
#define KW      197
#define NLAYERS 12
#define HIDDEN  3072
#define TOK     (BATCH*SEQ)       // 6304
#define BH      (BATCH*HEADS)     // 384
#define ROWSA   (BH*SEQ)          // 75648
#define SPAD    224               // padded stride for S and A rows
#define FCNPAD  208               // padded N stride for fc_w
#define KWPAD   208               // padded K for out/pv loops

#define CDIV(a,b) (((a)+(b)-1)/(b))

// ---------------- scratch ----------------
static __device__ float g_x1 [TOK*EMB];
static __device__ float g_x2 [TOK*EMB];
static __device__ float g_xn [TOK*EMB];
static __device__ float g_qkv[TOK*EMB3];
static __device__ float g_S  [(size_t)BH*SEQ*SPAD];
static __device__ float g_A  [(size_t)BH*SEQ*SPAD];
static __device__ float g_y  [BH*KW*HD];
static __device__ float g_h  [TOK*HIDDEN];
static __device__ float g_wqkv [EMB*EMB3];
static __device__ float g_wfc  [SPAD*FCNPAD];
static __device__ float g_w1   [EMB*HIDDEN];
static __device__ float g_w2   [HIDDEN*EMB];
static __device__ float g_wfc2t[256*KWPAD];   // fc2_w transposed [n2][k], padded

// ---------------- helpers ----------------
__device__ __forceinline__ uint32_t f2tf_u(float x) {
    uint32_t r; asm("cvt.rna.tf32.f32 %0, %1;" : "=r"(r) : "f"(x)); return r;
}
__device__ __forceinline__ float f2tf_f(float x) { return __uint_as_float(f2tf_u(x)); }

__device__ __forceinline__ void cpasync16(uint32_t dst, const void* src, int srcbytes) {
    asm volatile("cp.async.cg.shared.global [%0], [%1], 16, %2;\n"
                 :: "r"(dst), "l"(src), "r"(srcbytes));
}
__device__ __forceinline__ void cp_commit() { asm volatile("cp.async.commit_group;\n"); }
__device__ __forceinline__ void cp_wait0() { asm volatile("cp.async.wait_group 0;\n"); }

#define MMA_TF32(acc, afr, bfr)                                              \
    asm volatile(                                                            \
        "mma.sync.aligned.m16n8k8.row.col.f32.tf32.tf32.f32 "                \
        "{%0,%1,%2,%3}, {%4,%5,%6,%7}, {%8,%9}, {%0,%1,%2,%3};\n"            \
        : "+f"((acc)[0]), "+f"((acc)[1]), "+f"((acc)[2]), "+f"((acc)[3])     \
        : "r"((afr)[0]), "r"((afr)[1]), "r"((afr)[2]), "r"((afr)[3]),        \
          "r"((bfr)[0]), "r"((bfr)[1]))

// ---------------- elementwise ----------------
__global__ void init_copy(const float* __restrict__ x, float* __restrict__ x1,
                          float* __restrict__ x2, int n) {
    int i = blockIdx.x * blockDim.x + threadIdx.x;
    if (i < n) { float v = x[i]; x1[i] = v; x2[i] = v; }
}

__global__ void finalize_k(const float* __restrict__ x1, const float* __restrict__ x2,
                           float* __restrict__ out, int n) {
    int i = blockIdx.x * blockDim.x + threadIdx.x;
    if (i < n) out[i] = 0.5f * (x1[i] + x2[i]);
}

__global__ void prep_round(const float* __restrict__ s, float* __restrict__ d, int n) {
    int i = blockIdx.x * blockDim.x + threadIdx.x;
    if (i < n) d[i] = f2tf_f(s[i]);
}

__global__ void prep_fc(const float* __restrict__ s, float* __restrict__ d) {
    int i = blockIdx.x * blockDim.x + threadIdx.x;
    if (i < SPAD * FCNPAD) {
        int k = i / FCNPAD, n = i % FCNPAD;
        d[i] = (k < KW && n < SEQ) ? f2tf_f(s[k * SEQ + n]) : 0.f;
    }
}

__global__ void prep_fc2t(const float* __restrict__ s, float* __restrict__ d) {
    int i = blockIdx.x * blockDim.x + threadIdx.x;
    if (i < 256 * KWPAD) {
        int m = i / KWPAD, k = i % KWPAD;   // m = token col of fc2_w, k = KW row
        d[i] = (m < SEQ && k < KW) ? f2tf_f(s[k * SEQ + m]) : 0.f;
    }
}

__global__ void zero_pad_S(float* __restrict__ S) {
    int i = blockIdx.x * blockDim.x + threadIdx.x;
    const int padw = SPAD - KW;                 // 27
    if (i < ROWSA * padw) {
        int r = i / padw, c = KW + i % padw;
        S[(size_t)r * SPAD + c] = 0.f;
    }
}

// ---------------- layernorm rows of 768 (tf32-rounded out) ----------------
__global__ void ln_row768(const float* __restrict__ x, const float* __restrict__ g,
                          const float* __restrict__ b, float* __restrict__ out) {
    int row = blockIdx.x;
    const float* xr = x + (size_t)row * EMB;
    float* orow = out + (size_t)row * EMB;
    int tid = threadIdx.x;  // 256
    float s = 0.f, ss = 0.f;
    for (int i = tid; i < EMB; i += 256) { float v = xr[i]; s += v; ss += v * v; }
    __shared__ float rs[8], rss[8];
    #pragma unroll
    for (int o = 16; o; o >>= 1) {
        s  += __shfl_xor_sync(0xffffffffu, s,  o);
        ss += __shfl_xor_sync(0xffffffffu, ss, o);
    }
    if ((tid & 31) == 0) { rs[tid >> 5] = s; rss[tid >> 5] = ss; }
    __syncthreads();
    if (tid < 32) {
        float a = (tid < 8) ? rs[tid]  : 0.f;
        float c = (tid < 8) ? rss[tid] : 0.f;
        #pragma unroll
        for (int o = 4; o; o >>= 1) {
            a += __shfl_xor_sync(0xffffffffu, a, o);
            c += __shfl_xor_sync(0xffffffffu, c, o);
        }
        if (tid == 0) { rs[0] = a; rss[0] = c; }
    }
    __syncthreads();
    float mu  = rs[0] * (1.0f / EMB);
    float var = rss[0] * (1.0f / EMB) - mu * mu;
    float inv = rsqrtf(var + 1e-5f);
    for (int i = tid; i < EMB; i += 256)
        orow[i] = f2tf_f((xr[i] - mu) * inv * g[i] + b[i]);
}

// ================= big tf32 GEMM (128x128 tile, cp.async 2-stage) ==========
// EPI: 0 none | 1 +bias | 2 +bias,gelu,round | 3 +bias,+res | 4 round only
#define KCH 16
#define AS_STRIDE 20
#define BS_STRIDE 136
#define AS_STAGE (128*AS_STRIDE)
#define BS_STAGE (KCH*BS_STRIDE)

template <int EPI>
__global__ void __launch_bounds__(256) gemm_tf32(
    const float* __restrict__ A, const float* __restrict__ B, int ldb,
    const float* __restrict__ bias, const float* __restrict__ res,
    float* __restrict__ C, int ldc, int M, int N, int K)
{
    __shared__ float As[2 * AS_STAGE];
    __shared__ float Bs[2 * BS_STAGE];
    const int tid  = threadIdx.x;
    const int warp = tid >> 5, lane = tid & 31;
    const int wm = warp >> 2, wn = warp & 3;
    const int g = lane >> 2, t = lane & 3;
    const int m0 = blockIdx.y * 128, n0 = blockIdx.x * 128;

    const uint32_t as_u = (uint32_t)__cvta_generic_to_shared(As);
    const uint32_t bs_u = (uint32_t)__cvta_generic_to_shared(Bs);

    const int am0 = tid >> 2,  aseg = (tid & 3) * 4;
    const int am1 = (tid + 256) >> 2;
    const int bk0 = tid >> 5,  bseg = (tid & 31) * 4;
    const int bk1 = (tid + 256) >> 5;

    float acc[4][4][4];
    #pragma unroll
    for (int i = 0; i < 4; i++)
        #pragma unroll
        for (int j = 0; j < 4; j++)
            #pragma unroll
            for (int r = 0; r < 4; r++) acc[i][j][r] = 0.f;

    const int nch = K / KCH;
    {
        cpasync16(as_u + (size_t)(am0 * AS_STRIDE + aseg) * 4,
                  A + (size_t)(m0 + am0) * K + aseg, (m0 + am0 < M) ? 16 : 0);
        cpasync16(as_u + (size_t)(am1 * AS_STRIDE + aseg) * 4,
                  A + (size_t)(m0 + am1) * K + aseg, (m0 + am1 < M) ? 16 : 0);
        cpasync16(bs_u + (size_t)(bk0 * BS_STRIDE + bseg) * 4,
                  B + (size_t)bk0 * ldb + n0 + bseg, (n0 + bseg < ldb) ? 16 : 0);
        cpasync16(bs_u + (size_t)(bk1 * BS_STRIDE + bseg) * 4,
                  B + (size_t)bk1 * ldb + n0 + bseg, (n0 + bseg < ldb) ? 16 : 0);
        cp_commit();
    }

    for (int c = 0; c < nch; ++c) {
        if (c + 1 < nch) {
            const int k0 = (c + 1) * KCH;
            const int st = ((c + 1) & 1);
            cpasync16(as_u + (size_t)(st * AS_STAGE + am0 * AS_STRIDE + aseg) * 4,
                      A + (size_t)(m0 + am0) * K + k0 + aseg, (m0 + am0 < M) ? 16 : 0);
            cpasync16(as_u + (size_t)(st * AS_STAGE + am1 * AS_STRIDE + aseg) * 4,
                      A + (size_t)(m0 + am1) * K + k0 + aseg, (m0 + am1 < M) ? 16 : 0);
            cpasync16(bs_u + (size_t)(st * BS_STAGE + bk0 * BS_STRIDE + bseg) * 4,
                      B + (size_t)(k0 + bk0) * ldb + n0 + bseg, (n0 + bseg < ldb) ? 16 : 0);
            cpasync16(bs_u + (size_t)(st * BS_STAGE + bk1 * BS_STRIDE + bseg) * 4,
                      B + (size_t)(k0 + bk1) * ldb + n0 + bseg, (n0 + bseg < ldb) ? 16 : 0);
            cp_commit();
            asm volatile("cp.async.wait_group 1;\n");
        } else {
            cp_wait0();
        }
        __syncthreads();

        const uint32_t* as = (const uint32_t*)(As + (c & 1) * AS_STAGE);
        const uint32_t* bs = (const uint32_t*)(Bs + (c & 1) * BS_STAGE);

        #pragma unroll
        for (int kk = 0; kk < KCH / 8; ++kk) {
            const int kb = kk * 8;
            uint32_t afr[4][4];
            uint32_t bfr[4][2];
            #pragma unroll
            for (int mi = 0; mi < 4; mi++) {
                int m = wm * 64 + mi * 16 + g;
                afr[mi][0] = as[(m    ) * AS_STRIDE + kb + t    ];
                afr[mi][1] = as[(m + 8) * AS_STRIDE + kb + t    ];
                afr[mi][2] = as[(m    ) * AS_STRIDE + kb + t + 4];
                afr[mi][3] = as[(m + 8) * AS_STRIDE + kb + t + 4];
            }
            #pragma unroll
            for (int nj = 0; nj < 4; nj++) {
                int n = wn * 32 + nj * 8 + g;
                bfr[nj][0] = bs[(kb + t    ) * BS_STRIDE + n];
                bfr[nj][1] = bs[(kb + t + 4) * BS_STRIDE + n];
            }
            #pragma unroll
            for (int mi = 0; mi < 4; mi++)
                #pragma unroll
                for (int nj = 0; nj < 4; nj++)
                    MMA_TF32(acc[mi][nj], afr[mi], bfr[nj]);
        }
        __syncthreads();
    }

    #pragma unroll
    for (int mi = 0; mi < 4; mi++) {
        int r0 = m0 + wm * 64 + mi * 16 + g;
        #pragma unroll
        for (int nj = 0; nj < 4; nj++) {
            int cb = n0 + wn * 32 + nj * 8 + 2 * t;
            #pragma unroll
            for (int half = 0; half < 2; half++) {
                int gm = r0 + half * 8;
                if (gm >= M) continue;
                #pragma unroll
                for (int q = 0; q < 2; q++) {
                    int gn = cb + q;
                    if (gn >= N) continue;
                    float v = acc[mi][nj][half * 2 + q];
                    if (EPI == 1 || EPI == 2 || EPI == 3) v += bias[gn];
                    if (EPI == 2) {
                        v = 0.5f * v * (1.0f + erff(v * 0.70710678118654752f));
                        v = f2tf_f(v);
                    }
                    if (EPI == 3) v += res[(size_t)gm * ldc + gn];
                    if (EPI == 4) v = f2tf_f(v);
                    C[(size_t)gm * ldc + gn] = v;
                }
            }
        }
    }
}

// ---------------- QK^T, tf32 mma, per (b,h) ---------------------------------
// S[z, nq, mk] = 0.125 * sum_d Q[nq,d] K[mk,d]; output tf32-rounded, padded.
__global__ void __launch_bounds__(256) qk_tf32(const float* __restrict__ qkv,
                                               float* __restrict__ S)
{
    __shared__ float Qs[128][36];
    __shared__ float Ks[128][36];
    const int z = blockIdx.z, b = z / HEADS, h = z % HEADS;
    const float* qb = qkv + (size_t)b * SEQ * EMB3 + h * HD;
    const float* kb = qb + EMB;
    const int m0 = blockIdx.y * 128, n0 = blockIdx.x * 128;
    const int tid = threadIdx.x;
    const int warp = tid >> 5, lane = tid & 31;
    const int wm = warp >> 2, wn = warp & 3;
    const int g = lane >> 2, t = lane & 3;
    const uint32_t qs_u = (uint32_t)__cvta_generic_to_shared(Qs);
    const uint32_t ks_u = (uint32_t)__cvta_generic_to_shared(Ks);

    float acc[4][4][4];
    #pragma unroll
    for (int i = 0; i < 4; i++)
        #pragma unroll
        for (int j = 0; j < 4; j++)
            #pragma unroll
            for (int r = 0; r < 4; r++) acc[i][j][r] = 0.f;

    #pragma unroll
    for (int c = 0; c < 2; c++) {
        const int k0 = c * 32;
        #pragma unroll
        for (int i = 0; i < 4; i++) {
            int flat = tid + i * 256;
            int r = flat >> 3, sg = (flat & 7) * 4;
            int gq = m0 + r, gk = n0 + r;
            cpasync16(qs_u + (size_t)(r * 36 + sg) * 4,
                      qb + (size_t)gq * EMB3 + k0 + sg, (gq < SEQ) ? 16 : 0);
            cpasync16(ks_u + (size_t)(r * 36 + sg) * 4,
                      kb + (size_t)gk * EMB3 + k0 + sg, (gk < SEQ) ? 16 : 0);
        }
        cp_commit(); cp_wait0();
        __syncthreads();

        const uint32_t* qs = (const uint32_t*)Qs;
        const uint32_t* ks = (const uint32_t*)Ks;
        #pragma unroll
        for (int kk = 0; kk < 32; kk += 8) {
            uint32_t afr[4][4], bfr[4][2];
            #pragma unroll
            for (int mi = 0; mi < 4; mi++) {
                int m = wm * 64 + mi * 16 + g;
                afr[mi][0] = qs[(m    ) * 36 + kk + t    ];
                afr[mi][1] = qs[(m + 8) * 36 + kk + t    ];
                afr[mi][2] = qs[(m    ) * 36 + kk + t + 4];
                afr[mi][3] = qs[(m + 8) * 36 + kk + t + 4];
            }
            #pragma unroll
            for (int nj = 0; nj < 4; nj++) {
                int n = wn * 32 + nj * 8 + g;
                bfr[nj][0] = ks[n * 36 + kk + t    ];
                bfr[nj][1] = ks[n * 36 + kk + t + 4];
            }
            #pragma unroll
            for (int mi = 0; mi < 4; mi++)
                #pragma unroll
                for (int nj = 0; nj < 4; nj++)
                    MMA_TF32(acc[mi][nj], afr[mi], bfr[nj]);
        }
        __syncthreads();
    }

    float* Sz = S + (size_t)z * SEQ * SPAD;
    #pragma unroll
    for (int mi = 0; mi < 4; mi++) {
        int r0 = m0 + wm * 64 + mi * 16 + g;
        #pragma unroll
        for (int nj = 0; nj < 4; nj++) {
            int cb = n0 + wn * 32 + nj * 8 + 2 * t;
            #pragma unroll
            for (int half = 0; half < 2; half++) {
                int gm = r0 + half * 8;
                if (gm >= SEQ) continue;
                #pragma unroll
                for (int q = 0; q < 2; q++) {
                    int gn = cb + q;
                    if (gn >= SEQ) continue;
                    Sz[(size_t)gm * SPAD + gn] = f2tf_f(acc[mi][nj][half * 2 + q] * 0.125f);
                }
            }
        }
    }
}

// ---------------- fused LN(KW) + softmax(KW), warp per padded row ----------
__global__ void ln_softmax(float* __restrict__ A, const float* __restrict__ g,
                           const float* __restrict__ bb)
{
    int warp = (blockIdx.x * blockDim.x + threadIdx.x) >> 5;
    int lane = threadIdx.x & 31;
    if (warp >= ROWSA) return;
    float* row = A + (size_t)warp * SPAD;
    float v[7];
    float s = 0.f, ss = 0.f;
    #pragma unroll
    for (int i = 0; i < 7; i++) {
        int idx = lane + i * 32;
        v[i] = (idx < KW) ? row[idx] : 0.f;
        s += v[i]; ss += v[i] * v[i];
    }
    #pragma unroll
    for (int o = 16; o; o >>= 1) {
        s  += __shfl_xor_sync(0xffffffffu, s,  o);
        ss += __shfl_xor_sync(0xffffffffu, ss, o);
    }
    float mu  = s * (1.0f / KW);
    float var = ss * (1.0f / KW) - mu * mu;
    float inv = rsqrtf(var + 1e-5f);
    float mx = -1e30f;
    #pragma unroll
    for (int i = 0; i < 7; i++) {
        int idx = lane + i * 32;
        if (idx < KW) {
            float zv = (v[i] - mu) * inv * g[idx] + bb[idx];
            v[i] = zv;
            mx = fmaxf(mx, zv);
        } else v[i] = -1e30f;
    }
    #pragma unroll
    for (int o = 16; o; o >>= 1) mx = fmaxf(mx, __shfl_xor_sync(0xffffffffu, mx, o));
    float se = 0.f;
    #pragma unroll
    for (int i = 0; i < 7; i++) {
        int idx = lane + i * 32;
        float e = (idx < KW) ? __expf(v[i] - mx) : 0.f;
        v[i] = e; se += e;
    }
    #pragma unroll
    for (int o = 16; o; o >>= 1) se += __shfl_xor_sync(0xffffffffu, se, o);
    float r = 1.0f / se;
    #pragma unroll
    for (int i = 0; i < 7; i++) {
        int idx = lane + i * 32;
        if (idx < KW) row[idx] = f2tf_f(v[i] * r);
    }
}

// ---------------- P^T V, tf32 mma: y[z,kw,d] = sum_n P[n,kw] V[n,d] --------
__global__ void __launch_bounds__(256) pv_tf32(const float* __restrict__ A,
                                               const float* __restrict__ qkv,
                                               float* __restrict__ y)
{
    __shared__ float Ps[16][136];
    __shared__ float Vs[16][68];
    const int z = blockIdx.y, b = z / HEADS, h = z % HEADS;
    const float* Ab = A + (size_t)z * SEQ * SPAD;
    const float* Vb = qkv + (size_t)b * SEQ * EMB3 + h * HD + 2 * EMB;
    const int m0 = blockIdx.x * 128;
    const int tid = threadIdx.x;
    const int warp = tid >> 5, lane = tid & 31;
    const int wm = warp >> 1, wn = warp & 1;   // 4 x 2 warps: 32m x 32n
    const int g = lane >> 2, t = lane & 3;
    const uint32_t ps_u = (uint32_t)__cvta_generic_to_shared(Ps);
    const uint32_t vs_u = (uint32_t)__cvta_generic_to_shared(Vs);

    float acc[2][4][4];
    #pragma unroll
    for (int i = 0; i < 2; i++)
        #pragma unroll
        for (int j = 0; j < 4; j++)
            #pragma unroll
            for (int r = 0; r < 4; r++) acc[i][j][r] = 0.f;

    for (int c = 0; c < KWPAD / 16; ++c) {
        const int k0 = c * 16;
        #pragma unroll
        for (int i = 0; i < 2; i++) {
            int flat = tid + i * 256;
            int r = flat >> 5, sg = (flat & 31) * 4;
            int gk = k0 + r;
            cpasync16(ps_u + (size_t)(r * 136 + sg) * 4,
                      Ab + (size_t)gk * SPAD + m0 + sg,
                      (gk < SEQ && (m0 + sg) < SPAD) ? 16 : 0);
        }
        {
            int r = tid >> 4, sg = (tid & 15) * 4;
            int gk = k0 + r;
            cpasync16(vs_u + (size_t)(r * 68 + sg) * 4,
                      Vb + (size_t)gk * EMB3 + sg, (gk < SEQ) ? 16 : 0);
        }
        cp_commit(); cp_wait0();
        __syncthreads();

        const uint32_t* ps = (const uint32_t*)Ps;
        const uint32_t* vs = (const uint32_t*)Vs;
        #pragma unroll
        for (int kk = 0; kk < 16; kk += 8) {
            uint32_t afr[2][4], bfr[4][2];
            #pragma unroll
            for (int mi = 0; mi < 2; mi++) {
                int m = wm * 32 + mi * 16 + g;
                afr[mi][0] = ps[(kk + t    ) * 136 + m    ];
                afr[mi][1] = ps[(kk + t    ) * 136 + m + 8];
                afr[mi][2] = ps[(kk + t + 4) * 136 + m    ];
                afr[mi][3] = ps[(kk + t + 4) * 136 + m + 8];
            }
            #pragma unroll
            for (int nj = 0; nj < 4; nj++) {
                int n = wn * 32 + nj * 8 + g;
                bfr[nj][0] = vs[(kk + t    ) * 68 + n];
                bfr[nj][1] = vs[(kk + t + 4) * 68 + n];
            }
            #pragma unroll
            for (int mi = 0; mi < 2; mi++)
                #pragma unroll
                for (int nj = 0; nj < 4; nj++)
                    MMA_TF32(acc[mi][nj], afr[mi], bfr[nj]);
        }
        __syncthreads();
    }

    float* yz = y + (size_t)z * KW * HD;
    #pragma unroll
    for (int mi = 0; mi < 2; mi++) {
        int r0 = m0 + wm * 32 + mi * 16 + g;
        #pragma unroll
        for (int nj = 0; nj < 4; nj++) {
            int cb = wn * 32 + nj * 8 + 2 * t;
            #pragma unroll
            for (int half = 0; half < 2; half++) {
                int gm = r0 + half * 8;
                if (gm >= KW) continue;
                #pragma unroll
                for (int q = 0; q < 2; q++)
                    yz[(size_t)gm * HD + cb + q] = f2tf_f(acc[mi][nj][half * 2 + q]);
            }
        }
    }
}

// --------- fc2: x1[b,n2,h,d] += sum_k Wt[n2,k] y[z,k,d] + fc2_b[n2] --------
__global__ void __launch_bounds__(256) out_tf32(const float* __restrict__ Wt,
                                                const float* __restrict__ y,
                                                const float* __restrict__ bias,
                                                float* __restrict__ x1)
{
    __shared__ float As[128][20];
    __shared__ float Bs[16][68];
    const int z = blockIdx.y, b = z / HEADS, h = z % HEADS;
    const float* yb = y + (size_t)z * KW * HD;
    const int m0 = blockIdx.x * 128;
    const int tid = threadIdx.x;
    const int warp = tid >> 5, lane = tid & 31;
    const int wm = warp >> 1, wn = warp & 1;
    const int g = lane >> 2, t = lane & 3;
    const uint32_t as_u = (uint32_t)__cvta_generic_to_shared(As);
    const uint32_t bs_u = (uint32_t)__cvta_generic_to_shared(Bs);

    float acc[2][4][4];
    #pragma unroll
    for (int i = 0; i < 2; i++)
        #pragma unroll
        for (int j = 0; j < 4; j++)
            #pragma unroll
            for (int r = 0; r < 4; r++) acc[i][j][r] = 0.f;

    for (int c = 0; c < KWPAD / 16; ++c) {
        const int k0 = c * 16;
        #pragma unroll
        for (int i = 0; i < 2; i++) {
            int flat = tid + i * 256;
            int r = flat >> 2, sg = (flat & 3) * 4;
            cpasync16(as_u + (size_t)(r * 20 + sg) * 4,
                      Wt + (size_t)(m0 + r) * KWPAD + k0 + sg,
                      (m0 + r < SEQ) ? 16 : 0);
        }
        {
            int r = tid >> 4, sg = (tid & 15) * 4;
            int gk = k0 + r;
            cpasync16(bs_u + (size_t)(r * 68 + sg) * 4,
                      yb + (size_t)gk * HD + sg, (gk < KW) ? 16 : 0);
        }
        cp_commit(); cp_wait0();
        __syncthreads();

        const uint32_t* as = (const uint32_t*)As;
        const uint32_t* bs = (const uint32_t*)Bs;
        #pragma unroll
        for (int kk = 0; kk < 16; kk += 8) {
            uint32_t afr[2][4], bfr[4][2];
            #pragma unroll
            for (int mi = 0; mi < 2; mi++) {
                int m = wm * 32 + mi * 16 + g;
                afr[mi][0] = as[(m    ) * 20 + kk + t    ];
                afr[mi][1] = as[(m + 8) * 20 + kk + t    ];
                afr[mi][2] = as[(m    ) * 20 + kk + t + 4];
                afr[mi][3] = as[(m + 8) * 20 + kk + t + 4];
            }
            #pragma unroll
            for (int nj = 0; nj < 4; nj++) {
                int n = wn * 32 + nj * 8 + g;
                bfr[nj][0] = bs[(kk + t    ) * 68 + n];
                bfr[nj][1] = bs[(kk + t + 4) * 68 + n];
            }
            #pragma unroll
            for (int mi = 0; mi < 2; mi++)
                #pragma unroll
                for (int nj = 0; nj < 4; nj++)
                    MMA_TF32(acc[mi][nj], afr[mi], bfr[nj]);
        }
        __syncthreads();
    }

    #pragma unroll
    for (int mi = 0; mi < 2; mi++) {
        int r0 = m0 + wm * 32 + mi * 16 + g;
        #pragma unroll
        for (int nj = 0; nj < 4; nj++) {
            int cb = wn * 32 + nj * 8 + 2 * t;
            #pragma unroll
            for (int half = 0; half < 2; half++) {
                int gm = r0 + half * 8;
                if (gm >= SEQ) continue;
                float bv = bias[gm];
                #pragma unroll
                for (int q = 0; q < 2; q++) {
                    size_t idx = ((size_t)(b * SEQ + gm)) * EMB + h * HD + cb + q;
                    x1[idx] += acc[mi][nj][half * 2 + q] + bv;
                }
            }
        }
    }
}

// ---------------- launch ----------------
extern "C" void kernel_launch(void* const* d_in, const int* in_sizes, int n_in,
                              void* d_out, int out_size) {
    (void)in_sizes; (void)n_in; (void)out_size;
    const float* x         = (const float*)d_in[0];
    const float* qkv_w     = (const float*)d_in[1];
    const float* fc_w      = (const float*)d_in[2];
    const float* fc_b      = (const float*)d_in[3];
    const float* attn_ln_g = (const float*)d_in[4];
    const float* attn_ln_b = (const float*)d_in[5];
    const float* fc2_w     = (const float*)d_in[6];
    const float* fc2_b     = (const float*)d_in[7];
    const float* mlp_w1    = (const float*)d_in[8];
    const float* mlp_b1    = (const float*)d_in[9];
    const float* mlp_w2    = (const float*)d_in[10];
    const float* mlp_b2    = (const float*)d_in[11];
    const float* f_ln_g    = (const float*)d_in[12];
    const float* f_ln_b    = (const float*)d_in[13];
    const float* gl_ln_g   = (const float*)d_in[14];
    const float* gl_ln_b   = (const float*)d_in[15];

    float *px1, *px2, *pxn, *pqkv, *pS, *pA, *py, *ph;
    float *pwqkv, *pwfc, *pw1, *pw2, *pwfc2t;
    cudaGetSymbolAddress((void**)&px1,  g_x1);
    cudaGetSymbolAddress((void**)&px2,  g_x2);
    cudaGetSymbolAddress((void**)&pxn,  g_xn);
    cudaGetSymbolAddress((void**)&pqkv, g_qkv);
    cudaGetSymbolAddress((void**)&pS,   g_S);
    cudaGetSymbolAddress((void**)&pA,   g_A);
    cudaGetSymbolAddress((void**)&py,   g_y);
    cudaGetSymbolAddress((void**)&ph,   g_h);
    cudaGetSymbolAddress((void**)&pwqkv,  g_wqkv);
    cudaGetSymbolAddress((void**)&pwfc,   g_wfc);
    cudaGetSymbolAddress((void**)&pw1,    g_w1);
    cudaGetSymbolAddress((void**)&pw2,    g_w2);
    cudaGetSymbolAddress((void**)&pwfc2t, g_wfc2t);

    const int NE = TOK * EMB;

    prep_round<<<CDIV(EMB*EMB3, 256), 256>>>(qkv_w, pwqkv, EMB*EMB3);
    prep_round<<<CDIV(EMB*HIDDEN, 256), 256>>>(mlp_w1, pw1, EMB*HIDDEN);
    prep_round<<<CDIV(HIDDEN*EMB, 256), 256>>>(mlp_w2, pw2, HIDDEN*EMB);
    prep_fc<<<CDIV(SPAD*FCNPAD, 256), 256>>>(fc_w, pwfc);
    prep_fc2t<<<CDIV(256*KWPAD, 256), 256>>>(fc2_w, pwfc2t);
    zero_pad_S<<<CDIV(ROWSA*(SPAD-KW), 256), 256>>>(pS);

    init_copy<<<CDIV(NE, 256), 256>>>(x, px1, px2, NE);

    for (int l = 0; l < NLAYERS; ++l) {
        // y1 = x1 + attention(LN_f(x2))
        ln_row768<<<TOK, 256>>>(px2, f_ln_g + l * EMB, f_ln_b + l * EMB, pxn);
        gemm_tf32<4><<<dim3(CDIV(EMB3, 128), CDIV(TOK, 128)), 256>>>(
            pxn, pwqkv, EMB3, nullptr, nullptr, pqkv, EMB3, TOK, EMB3, EMB);
        qk_tf32<<<dim3(2, 2, BH), 256>>>(pqkv, pS);
        gemm_tf32<1><<<dim3(CDIV(KW, 128), CDIV(ROWSA, 128)), 256>>>(
            pS, pwfc, FCNPAD, fc_b, nullptr, pA, SPAD, ROWSA, KW, SPAD);
        ln_softmax<<<ROWSA / 8, 256>>>(pA, attn_ln_g, attn_ln_b);
        pv_tf32<<<dim3(2, BH), 256>>>(pA, pqkv, py);
        out_tf32<<<dim3(2, BH), 256>>>(pwfc2t, py, fc2_b, px1);
        // y2 = x2 + mlp(LN_g(y1))
        ln_row768<<<TOK, 256>>>(px1, gl_ln_g + l * EMB, gl_ln_b + l * EMB, pxn);
        gemm_tf32<2><<<dim3(CDIV(HIDDEN, 128), CDIV(TOK, 128)), 256>>>(
            pxn, pw1, HIDDEN, mlp_b1, nullptr, ph, HIDDEN, TOK, HIDDEN, EMB);
        gemm_tf32<3><<<dim3(CDIV(EMB, 128), CDIV(TOK, 128)), 256>>>(
            ph, pw2, EMB, mlp_b2, px2, px2, EMB, TOK, EMB, HIDDEN);
    }

    finalize_k<<<CDIV(NE, 256), 256>>>(px1, px2, (float*)d_out, NE);
}

// round 5
// speedup vs baseline: 5.0587x; 1.4067x over previous
#include <cuda_runtime.h>
#include <cuda_fp16.h>
#include <math.h>
#include <stdint.h>

#define BATCH   32
#define SEQ     197
#define EMB     768
#define EMB3    2304
#define HEADS   12
#define HD      64
#define KW      197
#define NLAYERS 12
#define HIDDEN  3072
#define TOK     (BATCH*SEQ)       // 6304
#define BH      (BATCH*HEADS)     // 384
#define ROWSA   (BH*SEQ)          // 75648
#define SPAD    224               // padded stride for S and A rows (halfs)
#define KWPAD   208               // padded K for out kernel

#define CDIV(a,b) (((a)+(b)-1)/(b))

// ---------------- scratch ----------------
static __device__ float  g_x1 [TOK*EMB];
static __device__ float  g_x2 [TOK*EMB];
static __device__ __half g_xn [TOK*EMB];
static __device__ __half g_qkv[TOK*EMB3];
static __device__ __half g_S  [(size_t)BH*SEQ*SPAD];
static __device__ __half g_A  [(size_t)BH*SEQ*SPAD];
static __device__ __half g_y  [BH*KW*HD];
static __device__ __half g_h  [TOK*HIDDEN];
// half weights, pre-transposed to [N][K]
static __device__ __half g_wqkv [EMB3*EMB];
static __device__ __half g_wfc  [256*SPAD];
static __device__ __half g_w1   [HIDDEN*EMB];
static __device__ __half g_w2   [EMB*HIDDEN];
static __device__ __half g_wfc2t[256*KWPAD];

// ---------------- helpers ----------------
__device__ __forceinline__ void cpasync16(uint32_t dst, const void* src, int srcbytes) {
    asm volatile("cp.async.cg.shared.global [%0], [%1], 16, %2;\n"
                 :: "r"(dst), "l"(src), "r"(srcbytes));
}
__device__ __forceinline__ void cp_commit() { asm volatile("cp.async.commit_group;\n"); }
__device__ __forceinline__ void cp_wait0() { asm volatile("cp.async.wait_group 0;\n"); }

#define MMA_F16(acc, afr, bfr)                                               \
    asm volatile(                                                            \
        "mma.sync.aligned.m16n8k16.row.col.f32.f16.f16.f32 "                 \
        "{%0,%1,%2,%3}, {%4,%5,%6,%7}, {%8,%9}, {%0,%1,%2,%3};\n"            \
        : "+f"((acc)[0]), "+f"((acc)[1]), "+f"((acc)[2]), "+f"((acc)[3])     \
        : "r"((afr)[0]), "r"((afr)[1]), "r"((afr)[2]), "r"((afr)[3]),        \
          "r"((bfr)[0]), "r"((bfr)[1]))

#define LDSM_X4_T(r0, r1, r2, r3, addr)                                      \
    asm volatile("ldmatrix.sync.aligned.m8n8.x4.trans.shared.b16 "           \
                 "{%0,%1,%2,%3}, [%4];"                                      \
                 : "=r"(r0), "=r"(r1), "=r"(r2), "=r"(r3) : "r"(addr))

// ---------------- elementwise ----------------
__global__ void init_copy(const float* __restrict__ x, float* __restrict__ x1,
                          float* __restrict__ x2, int n) {
    int i = blockIdx.x * blockDim.x + threadIdx.x;
    if (i < n) { float v = x[i]; x1[i] = v; x2[i] = v; }
}

__global__ void finalize_k(const float* __restrict__ x1, const float* __restrict__ x2,
                           float* __restrict__ out, int n) {
    int i = blockIdx.x * blockDim.x + threadIdx.x;
    if (i < n) out[i] = 0.5f * (x1[i] + x2[i]);
}

// transpose [K][N] float -> [N][K] half
__global__ void prep_wT(const float* __restrict__ s, __half* __restrict__ d,
                        int K, int N) {
    int i = blockIdx.x * blockDim.x + threadIdx.x;
    if (i < N * K) {
        int n = i / K, k = i % K;
        d[i] = __float2half_rn(s[(size_t)k * N + n]);
    }
}

// fc_w (SEQ,KW) -> Bt[256][SPAD]: Bt[n=kw][k=m]
__global__ void prep_fcT(const float* __restrict__ s, __half* __restrict__ d) {
    int i = blockIdx.x * blockDim.x + threadIdx.x;
    if (i < 256 * SPAD) {
        int n = i / SPAD, k = i % SPAD;
        d[i] = (n < KW && k < SEQ) ? __float2half_rn(s[k * KW + n]) : __float2half(0.f);
    }
}

// fc2_w (KW,SEQ) -> Wt[256][KWPAD]: Wt[n2][k=kw]
__global__ void prep_fc2T(const float* __restrict__ s, __half* __restrict__ d) {
    int i = blockIdx.x * blockDim.x + threadIdx.x;
    if (i < 256 * KWPAD) {
        int n2 = i / KWPAD, k = i % KWPAD;
        d[i] = (n2 < SEQ && k < KW) ? __float2half_rn(s[k * SEQ + n2]) : __float2half(0.f);
    }
}

__global__ void zero_pad_S(__half* __restrict__ S) {
    int i = blockIdx.x * blockDim.x + threadIdx.x;
    const int padw = SPAD - KW;
    if (i < ROWSA * padw) {
        int r = i / padw, c = KW + i % padw;
        S[(size_t)r * SPAD + c] = __float2half(0.f);
    }
}

// ---------------- layernorm rows of 768 -> half ----------------
__global__ void ln_row768(const float* __restrict__ x, const float* __restrict__ g,
                          const float* __restrict__ b, __half* __restrict__ out) {
    int row = blockIdx.x;
    const float* xr = x + (size_t)row * EMB;
    __half* orow = out + (size_t)row * EMB;
    int tid = threadIdx.x;  // 256
    float s = 0.f, ss = 0.f;
    for (int i = tid; i < EMB; i += 256) { float v = xr[i]; s += v; ss += v * v; }
    __shared__ float rs[8], rss[8];
    #pragma unroll
    for (int o = 16; o; o >>= 1) {
        s  += __shfl_xor_sync(0xffffffffu, s,  o);
        ss += __shfl_xor_sync(0xffffffffu, ss, o);
    }
    if ((tid & 31) == 0) { rs[tid >> 5] = s; rss[tid >> 5] = ss; }
    __syncthreads();
    if (tid < 32) {
        float a = (tid < 8) ? rs[tid]  : 0.f;
        float c = (tid < 8) ? rss[tid] : 0.f;
        #pragma unroll
        for (int o = 4; o; o >>= 1) {
            a += __shfl_xor_sync(0xffffffffu, a, o);
            c += __shfl_xor_sync(0xffffffffu, c, o);
        }
        if (tid == 0) { rs[0] = a; rss[0] = c; }
    }
    __syncthreads();
    float mu  = rs[0] * (1.0f / EMB);
    float var = rss[0] * (1.0f / EMB) - mu * mu;
    float inv = rsqrtf(var + 1e-5f);
    for (int i = tid; i < EMB; i += 256)
        orow[i] = __float2half_rn((xr[i] - mu) * inv * g[i] + b[i]);
}

// ================= fp16 GEMM: C = A[M,K] @ Bt[N,K]^T ======================
// 128x128x32 tiles, 2-stage cp.async, m16n8k16. B pre-transposed [N][K].
// EPI: 1 +bias->half | 2 +bias,gelu->half | 3 +bias,+res->float | 4 ->half
#define GST 40           // smem tile stride in halfs
#define GSTG (128*GST)   // stage size in halfs (5120)

template <int EPI>
__global__ void __launch_bounds__(256) gemm_f16(
    const __half* __restrict__ A, const __half* __restrict__ B,
    const float* __restrict__ bias, const float* __restrict__ res,
    __half* __restrict__ Ch, float* __restrict__ Cf,
    int ldc, int M, int N, int K)
{
    __shared__ __half As[2 * GSTG];
    __shared__ __half Bs[2 * GSTG];
    const int tid  = threadIdx.x;
    const int warp = tid >> 5, lane = tid & 31;
    const int wm = warp >> 2, wn = warp & 3;
    const int g = lane >> 2, t = lane & 3;
    const int m0 = blockIdx.y * 128, n0 = blockIdx.x * 128;

    const uint32_t as_u = (uint32_t)__cvta_generic_to_shared(As);
    const uint32_t bs_u = (uint32_t)__cvta_generic_to_shared(Bs);

    const int r0i = tid >> 2, seg = (tid & 3) * 8;
    const int r1i = (tid + 256) >> 2;

    float acc[4][4][4];
    #pragma unroll
    for (int i = 0; i < 4; i++)
        #pragma unroll
        for (int j = 0; j < 4; j++)
            #pragma unroll
            for (int r = 0; r < 4; r++) acc[i][j][r] = 0.f;

    const int nch = K / 32;

    // prefetch stage 0
    {
        cpasync16(as_u + (size_t)(r0i * GST + seg) * 2,
                  A + (size_t)(m0 + r0i) * K + seg, (m0 + r0i < M) ? 16 : 0);
        cpasync16(as_u + (size_t)(r1i * GST + seg) * 2,
                  A + (size_t)(m0 + r1i) * K + seg, (m0 + r1i < M) ? 16 : 0);
        cpasync16(bs_u + (size_t)(r0i * GST + seg) * 2,
                  B + (size_t)(n0 + r0i) * K + seg, 16);
        cpasync16(bs_u + (size_t)(r1i * GST + seg) * 2,
                  B + (size_t)(n0 + r1i) * K + seg, 16);
        cp_commit();
    }

    for (int c = 0; c < nch; ++c) {
        if (c + 1 < nch) {
            const int k0 = (c + 1) * 32;
            const int so = ((c + 1) & 1) * GSTG;
            cpasync16(as_u + (size_t)(so + r0i * GST + seg) * 2,
                      A + (size_t)(m0 + r0i) * K + k0 + seg, (m0 + r0i < M) ? 16 : 0);
            cpasync16(as_u + (size_t)(so + r1i * GST + seg) * 2,
                      A + (size_t)(m0 + r1i) * K + k0 + seg, (m0 + r1i < M) ? 16 : 0);
            cpasync16(bs_u + (size_t)(so + r0i * GST + seg) * 2,
                      B + (size_t)(n0 + r0i) * K + k0 + seg, 16);
            cpasync16(bs_u + (size_t)(so + r1i * GST + seg) * 2,
                      B + (size_t)(n0 + r1i) * K + k0 + seg, 16);
            cp_commit();
            asm volatile("cp.async.wait_group 1;\n");
        } else {
            cp_wait0();
        }
        __syncthreads();

        const uint32_t* as32 = (const uint32_t*)(As + (c & 1) * GSTG);
        const uint32_t* bs32 = (const uint32_t*)(Bs + (c & 1) * GSTG);

        #pragma unroll
        for (int kk = 0; kk < 2; ++kk) {
            const int kb2 = kk * 8;     // u32 offset of k16-step
            uint32_t afr[4][4], bfr[4][2];
            #pragma unroll
            for (int mi = 0; mi < 4; mi++) {
                int m = wm * 64 + mi * 16 + g;
                afr[mi][0] = as32[(m    ) * 20 + kb2 + t];
                afr[mi][1] = as32[(m + 8) * 20 + kb2 + t];
                afr[mi][2] = as32[(m    ) * 20 + kb2 + t + 4];
                afr[mi][3] = as32[(m + 8) * 20 + kb2 + t + 4];
            }
            #pragma unroll
            for (int nj = 0; nj < 4; nj++) {
                int n = wn * 32 + nj * 8 + g;
                bfr[nj][0] = bs32[n * 20 + kb2 + t];
                bfr[nj][1] = bs32[n * 20 + kb2 + t + 4];
            }
            #pragma unroll
            for (int mi = 0; mi < 4; mi++)
                #pragma unroll
                for (int nj = 0; nj < 4; nj++)
                    MMA_F16(acc[mi][nj], afr[mi], bfr[nj]);
        }
        __syncthreads();
    }

    #pragma unroll
    for (int mi = 0; mi < 4; mi++) {
        int r0 = m0 + wm * 64 + mi * 16 + g;
        #pragma unroll
        for (int nj = 0; nj < 4; nj++) {
            int cb = n0 + wn * 32 + nj * 8 + 2 * t;
            #pragma unroll
            for (int half_ = 0; half_ < 2; half_++) {
                int gm = r0 + half_ * 8;
                if (gm >= M) continue;
                #pragma unroll
                for (int q = 0; q < 2; q++) {
                    int gn = cb + q;
                    if (gn >= N) continue;
                    float v = acc[mi][nj][half_ * 2 + q];
                    if (EPI == 1 || EPI == 2 || EPI == 3) v += bias[gn];
                    if (EPI == 2)
                        v = 0.5f * v * (1.0f + erff(v * 0.70710678118654752f));
                    if (EPI == 3)
                        Cf[(size_t)gm * ldc + gn] = v + res[(size_t)gm * ldc + gn];
                    else
                        Ch[(size_t)gm * ldc + gn] = __float2half_rn(v);
                }
            }
        }
    }
}

// ---------------- QK^T fp16 mma per (b,h): 128x128, K=64 -------------------
__global__ void __launch_bounds__(256) qk_f16(const __half* __restrict__ qkv,
                                              __half* __restrict__ S)
{
    __shared__ __half Qs[128 * 72];
    __shared__ __half Ks[128 * 72];
    const int z = blockIdx.z, b = z / HEADS, h = z % HEADS;
    const __half* qb = qkv + (size_t)b * SEQ * EMB3 + h * HD;
    const __half* kb = qb + EMB;
    const int m0 = blockIdx.y * 128, n0 = blockIdx.x * 128;
    const int tid = threadIdx.x;
    const int warp = tid >> 5, lane = tid & 31;
    const int wm = warp >> 2, wn = warp & 3;
    const int g = lane >> 2, t = lane & 3;
    const uint32_t qs_u = (uint32_t)__cvta_generic_to_shared(Qs);
    const uint32_t ks_u = (uint32_t)__cvta_generic_to_shared(Ks);

    #pragma unroll
    for (int i = 0; i < 4; i++) {
        int s = tid + i * 256;
        int r = s >> 3, sg = (s & 7) * 8;
        cpasync16(qs_u + (size_t)(r * 72 + sg) * 2,
                  qb + (size_t)(m0 + r) * EMB3 + sg, (m0 + r < SEQ) ? 16 : 0);
        cpasync16(ks_u + (size_t)(r * 72 + sg) * 2,
                  kb + (size_t)(n0 + r) * EMB3 + sg, (n0 + r < SEQ) ? 16 : 0);
    }
    cp_commit(); cp_wait0();
    __syncthreads();

    float acc[4][4][4];
    #pragma unroll
    for (int i = 0; i < 4; i++)
        #pragma unroll
        for (int j = 0; j < 4; j++)
            #pragma unroll
            for (int r = 0; r < 4; r++) acc[i][j][r] = 0.f;

    const uint32_t* qs32 = (const uint32_t*)Qs;
    const uint32_t* ks32 = (const uint32_t*)Ks;
    #pragma unroll
    for (int kk = 0; kk < 4; ++kk) {
        const int kb2 = kk * 8;
        uint32_t afr[4][4], bfr[4][2];
        #pragma unroll
        for (int mi = 0; mi < 4; mi++) {
            int m = wm * 64 + mi * 16 + g;
            afr[mi][0] = qs32[(m    ) * 36 + kb2 + t];
            afr[mi][1] = qs32[(m + 8) * 36 + kb2 + t];
            afr[mi][2] = qs32[(m    ) * 36 + kb2 + t + 4];
            afr[mi][3] = qs32[(m + 8) * 36 + kb2 + t + 4];
        }
        #pragma unroll
        for (int nj = 0; nj < 4; nj++) {
            int n = wn * 32 + nj * 8 + g;
            bfr[nj][0] = ks32[n * 36 + kb2 + t];
            bfr[nj][1] = ks32[n * 36 + kb2 + t + 4];
        }
        #pragma unroll
        for (int mi = 0; mi < 4; mi++)
            #pragma unroll
            for (int nj = 0; nj < 4; nj++)
                MMA_F16(acc[mi][nj], afr[mi], bfr[nj]);
    }

    __half* Sz = S + (size_t)z * SEQ * SPAD;
    #pragma unroll
    for (int mi = 0; mi < 4; mi++) {
        int r0 = m0 + wm * 64 + mi * 16 + g;
        #pragma unroll
        for (int nj = 0; nj < 4; nj++) {
            int cb = n0 + wn * 32 + nj * 8 + 2 * t;
            #pragma unroll
            for (int half_ = 0; half_ < 2; half_++) {
                int gm = r0 + half_ * 8;
                if (gm >= SEQ) continue;
                #pragma unroll
                for (int q = 0; q < 2; q++) {
                    int gn = cb + q;
                    if (gn >= SEQ) continue;
                    Sz[(size_t)gm * SPAD + gn] =
                        __float2half_rn(acc[mi][nj][half_ * 2 + q] * 0.125f);
                }
            }
        }
    }
}

// ---------------- fused LN(KW) + softmax(KW), warp per row (half) ----------
__global__ void ln_softmax(__half* __restrict__ A, const float* __restrict__ g,
                           const float* __restrict__ bb)
{
    int warp = (blockIdx.x * blockDim.x + threadIdx.x) >> 5;
    int lane = threadIdx.x & 31;
    if (warp >= ROWSA) return;
    __half* row = A + (size_t)warp * SPAD;
    float v[7];
    float s = 0.f, ss = 0.f;
    #pragma unroll
    for (int i = 0; i < 7; i++) {
        int idx = lane + i * 32;
        v[i] = (idx < KW) ? __half2float(row[idx]) : 0.f;
        s += v[i]; ss += v[i] * v[i];
    }
    #pragma unroll
    for (int o = 16; o; o >>= 1) {
        s  += __shfl_xor_sync(0xffffffffu, s,  o);
        ss += __shfl_xor_sync(0xffffffffu, ss, o);
    }
    float mu  = s * (1.0f / KW);
    float var = ss * (1.0f / KW) - mu * mu;
    float inv = rsqrtf(var + 1e-5f);
    float mx = -1e30f;
    #pragma unroll
    for (int i = 0; i < 7; i++) {
        int idx = lane + i * 32;
        if (idx < KW) {
            float zv = (v[i] - mu) * inv * g[idx] + bb[idx];
            v[i] = zv;
            mx = fmaxf(mx, zv);
        } else v[i] = -1e30f;
    }
    #pragma unroll
    for (int o = 16; o; o >>= 1) mx = fmaxf(mx, __shfl_xor_sync(0xffffffffu, mx, o));
    float se = 0.f;
    #pragma unroll
    for (int i = 0; i < 7; i++) {
        int idx = lane + i * 32;
        float e = (idx < KW) ? __expf(v[i] - mx) : 0.f;
        v[i] = e; se += e;
    }
    #pragma unroll
    for (int o = 16; o; o >>= 1) se += __shfl_xor_sync(0xffffffffu, se, o);
    float r = 1.0f / se;
    #pragma unroll
    for (int i = 0; i < 7; i++) {
        int idx = lane + i * 32;
        if (idx < KW) row[idx] = __float2half_rn(v[i] * r);
    }
}

// ---------------- P^T V fp16: y[z,kw,d] = sum_n P[n,kw] V[n,d] -------------
__global__ void __launch_bounds__(256) pv_f16(const __half* __restrict__ A,
                                              const __half* __restrict__ qkv,
                                              __half* __restrict__ y)
{
    __shared__ __half Ps[16 * 136];
    __shared__ __half Vs[16 * 72];
    const int z = blockIdx.y, b = z / HEADS, h = z % HEADS;
    const __half* Ab = A + (size_t)z * SEQ * SPAD;
    const __half* Vb = qkv + (size_t)b * SEQ * EMB3 + h * HD + 2 * EMB;
    const int m0 = blockIdx.x * 128;
    const int tid = threadIdx.x;
    const int warp = tid >> 5, lane = tid & 31;
    const int wm = warp >> 1, wn = warp & 1;    // 4m x 2n warps; 32x32 each
    const int g = lane >> 2, t = lane & 3;
    const uint32_t ps_u = (uint32_t)__cvta_generic_to_shared(Ps);
    const uint32_t vs_u = (uint32_t)__cvta_generic_to_shared(Vs);

    // ldmatrix lane mappings
    const int arow = (lane & 7) + ((lane >> 4) << 3);        // A: +8 rows if lane>=16
    const int acol8 = ((lane >> 3) & 1) << 3;                 // A: +8 cols if bit3
    const int brow = (lane & 7) + (((lane >> 3) & 1) << 3);  // B: +8 rows if bit3
    const int bcol8 = (lane >> 4) << 3;                       // B: +8 cols if lane>=16

    float acc[2][4][4];
    #pragma unroll
    for (int i = 0; i < 2; i++)
        #pragma unroll
        for (int j = 0; j < 4; j++)
            #pragma unroll
            for (int r = 0; r < 4; r++) acc[i][j][r] = 0.f;

    for (int c = 0; c < KWPAD / 16; ++c) {
        const int k0 = c * 16;
        {   // P chunk: 16 rows x 128 halfs (cols = kw)
            int r = tid >> 4, sg = (tid & 15) * 8;
            cpasync16(ps_u + (size_t)(r * 136 + sg) * 2,
                      Ab + (size_t)(k0 + r) * SPAD + m0 + sg,
                      (k0 + r < SEQ && m0 + sg < SPAD) ? 16 : 0);
        }
        if (tid < 128) {  // V chunk: 16 rows x 64 halfs
            int r = tid >> 3, sg = (tid & 7) * 8;
            cpasync16(vs_u + (size_t)(r * 72 + sg) * 2,
                      Vb + (size_t)(k0 + r) * EMB3 + sg, (k0 + r < SEQ) ? 16 : 0);
        }
        cp_commit(); cp_wait0();
        __syncthreads();

        uint32_t afr[2][4], bfr[4][2];
        #pragma unroll
        for (int mi = 0; mi < 2; mi++) {
            uint32_t addr = ps_u + (size_t)(arow * 136 + wm * 32 + mi * 16 + acol8) * 2;
            LDSM_X4_T(afr[mi][0], afr[mi][1], afr[mi][2], afr[mi][3], addr);
        }
        #pragma unroll
        for (int njp = 0; njp < 2; njp++) {
            uint32_t addr = vs_u + (size_t)(brow * 72 + wn * 32 + njp * 16 + bcol8) * 2;
            LDSM_X4_T(bfr[njp * 2][0], bfr[njp * 2][1],
                      bfr[njp * 2 + 1][0], bfr[njp * 2 + 1][1], addr);
        }
        #pragma unroll
        for (int mi = 0; mi < 2; mi++)
            #pragma unroll
            for (int nj = 0; nj < 4; nj++)
                MMA_F16(acc[mi][nj], afr[mi], bfr[nj]);
        __syncthreads();
    }

    __half* yz = y + (size_t)z * KW * HD;
    #pragma unroll
    for (int mi = 0; mi < 2; mi++) {
        int r0 = m0 + wm * 32 + mi * 16 + g;
        #pragma unroll
        for (int nj = 0; nj < 4; nj++) {
            int cb = wn * 32 + nj * 8 + 2 * t;
            #pragma unroll
            for (int half_ = 0; half_ < 2; half_++) {
                int gm = r0 + half_ * 8;
                if (gm >= KW) continue;
                #pragma unroll
                for (int q = 0; q < 2; q++)
                    yz[(size_t)gm * HD + cb + q] =
                        __float2half_rn(acc[mi][nj][half_ * 2 + q]);
            }
        }
    }
}

// --------- fc2: x1[b,n2,h,d] += sum_k Wt[n2,k] y[z,k,d] + fc2_b[n2] --------
__global__ void __launch_bounds__(256) out_f16(const __half* __restrict__ Wt,
                                               const __half* __restrict__ y,
                                               const float* __restrict__ bias,
                                               float* __restrict__ x1)
{
    __shared__ __half As[128 * 24];
    __shared__ __half Ys[16 * 72];
    const int z = blockIdx.y, b = z / HEADS, h = z % HEADS;
    const __half* yb = y + (size_t)z * KW * HD;
    const int m0 = blockIdx.x * 128;
    const int tid = threadIdx.x;
    const int warp = tid >> 5, lane = tid & 31;
    const int wm = warp >> 1, wn = warp & 1;
    const int g = lane >> 2, t = lane & 3;
    const uint32_t as_u = (uint32_t)__cvta_generic_to_shared(As);
    const uint32_t ys_u = (uint32_t)__cvta_generic_to_shared(Ys);

    const int brow = (lane & 7) + (((lane >> 3) & 1) << 3);
    const int bcol8 = (lane >> 4) << 3;

    float acc[2][4][4];
    #pragma unroll
    for (int i = 0; i < 2; i++)
        #pragma unroll
        for (int j = 0; j < 4; j++)
            #pragma unroll
            for (int r = 0; r < 4; r++) acc[i][j][r] = 0.f;

    for (int c = 0; c < KWPAD / 16; ++c) {
        const int k0 = c * 16;
        {   // Wt chunk: 128 rows x 16 halfs
            int r = tid >> 1, sg = (tid & 1) * 8;
            cpasync16(as_u + (size_t)(r * 24 + sg) * 2,
                      Wt + (size_t)(m0 + r) * KWPAD + k0 + sg, 16);
        }
        if (tid < 128) {  // y chunk: 16 rows x 64 halfs
            int r = tid >> 3, sg = (tid & 7) * 8;
            cpasync16(ys_u + (size_t)(r * 72 + sg) * 2,
                      yb + (size_t)(k0 + r) * HD + sg, (k0 + r < KW) ? 16 : 0);
        }
        cp_commit(); cp_wait0();
        __syncthreads();

        const uint32_t* as32 = (const uint32_t*)As;
        uint32_t afr[2][4], bfr[4][2];
        #pragma unroll
        for (int mi = 0; mi < 2; mi++) {
            int m = wm * 32 + mi * 16 + g;
            afr[mi][0] = as32[(m    ) * 12 + t];
            afr[mi][1] = as32[(m + 8) * 12 + t];
            afr[mi][2] = as32[(m    ) * 12 + t + 4];
            afr[mi][3] = as32[(m + 8) * 12 + t + 4];
        }
        #pragma unroll
        for (int njp = 0; njp < 2; njp++) {
            uint32_t addr = ys_u + (size_t)(brow * 72 + wn * 32 + njp * 16 + bcol8) * 2;
            LDSM_X4_T(bfr[njp * 2][0], bfr[njp * 2][1],
                      bfr[njp * 2 + 1][0], bfr[njp * 2 + 1][1], addr);
        }
        #pragma unroll
        for (int mi = 0; mi < 2; mi++)
            #pragma unroll
            for (int nj = 0; nj < 4; nj++)
                MMA_F16(acc[mi][nj], afr[mi], bfr[nj]);
        __syncthreads();
    }

    #pragma unroll
    for (int mi = 0; mi < 2; mi++) {
        int r0 = m0 + wm * 32 + mi * 16 + g;
        #pragma unroll
        for (int nj = 0; nj < 4; nj++) {
            int cb = wn * 32 + nj * 8 + 2 * t;
            #pragma unroll
            for (int half_ = 0; half_ < 2; half_++) {
                int gm = r0 + half_ * 8;
                if (gm >= SEQ) continue;
                float bv = bias[gm];
                #pragma unroll
                for (int q = 0; q < 2; q++) {
                    size_t idx = ((size_t)(b * SEQ + gm)) * EMB + h * HD + cb + q;
                    x1[idx] += acc[mi][nj][half_ * 2 + q] + bv;
                }
            }
        }
    }
}

// ---------------- launch ----------------
extern "C" void kernel_launch(void* const* d_in, const int* in_sizes, int n_in,
                              void* d_out, int out_size) {
    (void)in_sizes; (void)n_in; (void)out_size;
    const float* x         = (const float*)d_in[0];
    const float* qkv_w     = (const float*)d_in[1];
    const float* fc_w      = (const float*)d_in[2];
    const float* fc_b      = (const float*)d_in[3];
    const float* attn_ln_g = (const float*)d_in[4];
    const float* attn_ln_b = (const float*)d_in[5];
    const float* fc2_w     = (const float*)d_in[6];
    const float* fc2_b     = (const float*)d_in[7];
    const float* mlp_w1    = (const float*)d_in[8];
    const float* mlp_b1    = (const float*)d_in[9];
    const float* mlp_w2    = (const float*)d_in[10];
    const float* mlp_b2    = (const float*)d_in[11];
    const float* f_ln_g    = (const float*)d_in[12];
    const float* f_ln_b    = (const float*)d_in[13];
    const float* gl_ln_g   = (const float*)d_in[14];
    const float* gl_ln_b   = (const float*)d_in[15];

    float *px1, *px2;
    __half *pxn, *pqkv, *pS, *pA, *py, *ph;
    __half *pwqkv, *pwfc, *pw1, *pw2, *pwfc2t;
    cudaGetSymbolAddress((void**)&px1,  g_x1);
    cudaGetSymbolAddress((void**)&px2,  g_x2);
    cudaGetSymbolAddress((void**)&pxn,  g_xn);
    cudaGetSymbolAddress((void**)&pqkv, g_qkv);
    cudaGetSymbolAddress((void**)&pS,   g_S);
    cudaGetSymbolAddress((void**)&pA,   g_A);
    cudaGetSymbolAddress((void**)&py,   g_y);
    cudaGetSymbolAddress((void**)&ph,   g_h);
    cudaGetSymbolAddress((void**)&pwqkv,  g_wqkv);
    cudaGetSymbolAddress((void**)&pwfc,   g_wfc);
    cudaGetSymbolAddress((void**)&pw1,    g_w1);
    cudaGetSymbolAddress((void**)&pw2,    g_w2);
    cudaGetSymbolAddress((void**)&pwfc2t, g_wfc2t);

    const int NE = TOK * EMB;

    prep_wT<<<CDIV(EMB*EMB3, 256), 256>>>(qkv_w, pwqkv, EMB, EMB3);
    prep_wT<<<CDIV(EMB*HIDDEN, 256), 256>>>(mlp_w1, pw1, EMB, HIDDEN);
    prep_wT<<<CDIV(HIDDEN*EMB, 256), 256>>>(mlp_w2, pw2, HIDDEN, EMB);
    prep_fcT<<<CDIV(256*SPAD, 256), 256>>>(fc_w, pwfc);
    prep_fc2T<<<CDIV(256*KWPAD, 256), 256>>>(fc2_w, pwfc2t);
    zero_pad_S<<<CDIV(ROWSA*(SPAD-KW), 256), 256>>>(pS);

    init_copy<<<CDIV(NE, 256), 256>>>(x, px1, px2, NE);

    for (int l = 0; l < NLAYERS; ++l) {
        // y1 = x1 + attention(LN_f(x2))
        ln_row768<<<TOK, 256>>>(px2, f_ln_g + l * EMB, f_ln_b + l * EMB, pxn);
        gemm_f16<4><<<dim3(EMB3/128, CDIV(TOK,128)), 256>>>(
            pxn, pwqkv, nullptr, nullptr, pqkv, nullptr, EMB3, TOK, EMB3, EMB);
        qk_f16<<<dim3(2, 2, BH), 256>>>(pqkv, pS);
        gemm_f16<1><<<dim3(CDIV(KW,128), CDIV(ROWSA,128)), 256>>>(
            pS, pwfc, fc_b, nullptr, pA, nullptr, SPAD, ROWSA, KW, SPAD);
        ln_softmax<<<ROWSA / 8, 256>>>(pA, attn_ln_g, attn_ln_b);
        pv_f16<<<dim3(2, BH), 256>>>(pA, pqkv, py);
        out_f16<<<dim3(2, BH), 256>>>(pwfc2t, py, fc2_b, px1);
        // y2 = x2 + mlp(LN_g(y1))
        ln_row768<<<TOK, 256>>>(px1, gl_ln_g + l * EMB, gl_ln_b + l * EMB, pxn);
        gemm_f16<2><<<dim3(HIDDEN/128, CDIV(TOK,128)), 256>>>(
            pxn, pw1, mlp_b1, nullptr, ph, nullptr, HIDDEN, TOK, HIDDEN, EMB);
        gemm_f16<3><<<dim3(EMB/128, CDIV(TOK,128)), 256>>>(
            ph, pw2, mlp_b2, px2, nullptr, px2, EMB, TOK, EMB, HIDDEN);
    }

    finalize_k<<<CDIV(NE, 256), 256>>>(px1, px2, (float*)d_out, NE);
}